// round 3
// baseline (speedup 1.0000x reference)
#include <cuda_runtime.h>
#include <math.h>

// Problem constants
// B=4, N=4096, DIM=1024, HEADS=16, DIM_HEAD=64, M=128, DIM_INNER=1024
// qkv layout: [b, n, 3*1024] with col = qkv_idx*1024 + h*64 + d
#define SCALE_A 0.125f   // 64^-0.5

// ---------------- scratch (device globals; no runtime allocation) ----------------
__device__ float g_qkv[50331648];    // [4,4096,3072]
__device__ float g_qa[33554432];     // qa_attn  [b,h,m=128,n=4096]  (n fastest)
__device__ float g_qam[33554432];    // qa mixed [b,g,m,n]
__device__ float g_ak[33554432];     // ak_sim/attn [b,h,m,n]
__device__ float g_akm[33554432];    // ak mixed [b,g,m,n]
__device__ float g_ao[524288];       // agent_out [b,g,m=128,d=64]
__device__ float g_outpre[16777216]; // [b,n,1024] pre-projection, masked
__device__ unsigned char g_mask[16384]; // canonical uint8 mask [b,n]

// ---------------- mask canonicalization ----------------
// The harness may deliver the jax bool mask as uint8, int32, or float32.
// Sniff the first 16384 bytes (valid under every interpretation) and expand
// to canonical uint8. Single block; deterministic.
__global__ void k_mask_canon(const void* __restrict__ mraw) {
    __shared__ int notI32, notF32;
    if (threadIdx.x == 0) { notI32 = 0; notF32 = 0; }
    __syncthreads();
    const unsigned int* w = (const unsigned int*)mraw;
    int a = 0, b = 0;
    for (int i = threadIdx.x; i < 4096; i += 256) {
        unsigned int v = w[i];                      // first 16KB only
        if (v > 1u) a = 1;
        if (v != 0u && v != 0x3F800000u) b = 1;
    }
    if (a) atomicOr(&notI32, 1);
    if (b) atomicOr(&notF32, 1);
    __syncthreads();
    const int mode = notI32 ? (notF32 ? 2 : 1) : 0; // 0=int32, 1=float32, 2=uint8
    for (int i = threadIdx.x; i < 16384; i += 256) {
        unsigned char mv;
        if (mode == 0)      mv = (((const int*)mraw)[i] != 0);
        else if (mode == 1) mv = (((const float*)mraw)[i] != 0.0f);
        else                mv = (((const unsigned char*)mraw)[i] != 0);
        g_mask[i] = mv;
    }
}

// ---------------- generic fp32 SGEMM body: C[M,N] = A[M,K] @ B[K,N] ----------------
// BM=BN=128, BK=16, 256 threads, 8x8 per thread. M%128==0, N%128==0, K%16==0.
__device__ __forceinline__ void sgemm_body(const float* __restrict__ A,
                                           const float* __restrict__ B,
                                           float* __restrict__ C,
                                           int M, int N, int K) {
    __shared__ float As[16][128];   // transposed A tile
    __shared__ float Bs[16][128];
    const int tid = threadIdx.x;
    const int m0 = blockIdx.y * 128;
    const int n0 = blockIdx.x * 128;
    const int tx = tid & 15;        // 0..15
    const int ty = tid >> 4;        // 0..15

    const int aRow = tid >> 2;            // 0..63
    const int aCol = (tid & 3) * 4;       // 0,4,8,12
    const int bRow = tid >> 5;            // 0..7
    const int bCol = (tid & 31) * 4;      // 0..124

    const float* Ab = A + (size_t)m0 * K;
    const float* Bb = B + n0;

    float acc[8][8];
#pragma unroll
    for (int i = 0; i < 8; i++)
#pragma unroll
        for (int j = 0; j < 8; j++) acc[i][j] = 0.f;

    for (int k0 = 0; k0 < K; k0 += 16) {
#pragma unroll
        for (int i = 0; i < 2; i++) {
            int r = aRow + i * 64;
            float4 v = *(const float4*)(Ab + (size_t)r * K + k0 + aCol);
            As[aCol + 0][r] = v.x;
            As[aCol + 1][r] = v.y;
            As[aCol + 2][r] = v.z;
            As[aCol + 3][r] = v.w;
        }
#pragma unroll
        for (int i = 0; i < 2; i++) {
            int r = bRow + i * 8;
            *(float4*)(&Bs[r][bCol]) = *(const float4*)(Bb + (size_t)(k0 + r) * N + bCol);
        }
        __syncthreads();
#pragma unroll
        for (int kk = 0; kk < 16; kk++) {
            float ra[8], rb[8];
            ((float4*)ra)[0] = *(const float4*)(&As[kk][ty * 8]);
            ((float4*)ra)[1] = *(const float4*)(&As[kk][ty * 8 + 4]);
            ((float4*)rb)[0] = *(const float4*)(&Bs[kk][tx * 8]);
            ((float4*)rb)[1] = *(const float4*)(&Bs[kk][tx * 8 + 4]);
#pragma unroll
            for (int i = 0; i < 8; i++)
#pragma unroll
                for (int j = 0; j < 8; j++) acc[i][j] += ra[i] * rb[j];
        }
        __syncthreads();
    }

    float* Cb = C + (size_t)m0 * N + n0;
#pragma unroll
    for (int i = 0; i < 8; i++) {
#pragma unroll
        for (int j = 0; j < 8; j += 4) {
            float4 v = make_float4(acc[i][j], acc[i][j + 1], acc[i][j + 2], acc[i][j + 3]);
            *(float4*)(Cb + (size_t)(ty * 8 + i) * N + tx * 8 + j) = v;
        }
    }
}

__global__ __launch_bounds__(256) void k_qkv_gemm(const float* __restrict__ x,
                                                  const float* __restrict__ Wqkv) {
    sgemm_body(x, Wqkv, g_qkv, 16384, 3072, 1024);
}

__global__ __launch_bounds__(256) void k_out_gemm(const float* __restrict__ Wout,
                                                  float* __restrict__ out) {
    sgemm_body(g_outpre, Wout, out, 16384, 1024, 1024);
}

// ---------------- qa: sim + softmax(over m), store [b,h,m,n] ----------------
// grid (32 ntiles, 16 h, 4 b), block 128. thread t -> row n = n0 + t.
__global__ __launch_bounds__(128) void k_qa(const float* __restrict__ agent) {
    __shared__ float a_s[128 * 64];
    const int b = blockIdx.z, h = blockIdx.y, n0 = blockIdx.x * 128;
    const int t = threadIdx.x;
    for (int i = t; i < 128 * 64; i += 128) a_s[i] = agent[h * 8192 + i] * SCALE_A;
    __syncthreads();

    const int n = n0 + t;
    const float4* qrow = (const float4*)(g_qkv + ((size_t)(b * 4096 + n)) * 3072 + h * 64);
    float4 q[16];
#pragma unroll
    for (int i = 0; i < 16; i++) q[i] = qrow[i];

    float mx = -3.402823e38f, sum = 0.f;
    for (int m = 0; m < 128; m++) {
        const float4* av = (const float4*)(a_s + m * 64);
        float s = 0.f;
#pragma unroll
        for (int i = 0; i < 16; i++) {
            float4 a4 = av[i];
            s += q[i].x * a4.x; s += q[i].y * a4.y;
            s += q[i].z * a4.z; s += q[i].w * a4.w;
        }
        float nm = fmaxf(mx, s);
        sum = sum * __expf(mx - nm) + __expf(s - nm);
        mx = nm;
    }
    const float inv = 1.f / sum;
    float* out = g_qa + ((size_t)(b * 16 + h) * 128) * 4096 + n;
    for (int m = 0; m < 128; m++) {
        const float4* av = (const float4*)(a_s + m * 64);
        float s = 0.f;
#pragma unroll
        for (int i = 0; i < 16; i++) {
            float4 a4 = av[i];
            s += q[i].x * a4.x; s += q[i].y * a4.y;
            s += q[i].z * a4.z; s += q[i].w * a4.w;
        }
        out[(size_t)m * 4096] = __expf(s - mx) * inv;
    }
}

// ---------------- ak: raw sims [b,h,m,n] ----------------
__global__ __launch_bounds__(128) void k_ak_sim(const float* __restrict__ agent) {
    __shared__ float a_s[128 * 64];
    const int b = blockIdx.z, h = blockIdx.y, n0 = blockIdx.x * 128;
    const int t = threadIdx.x;
    for (int i = t; i < 128 * 64; i += 128) a_s[i] = agent[h * 8192 + i] * SCALE_A;
    __syncthreads();

    const int n = n0 + t;
    const float4* krow = (const float4*)(g_qkv + ((size_t)(b * 4096 + n)) * 3072 + 1024 + h * 64);
    float4 k[16];
#pragma unroll
    for (int i = 0; i < 16; i++) k[i] = krow[i];

    float* out = g_ak + ((size_t)(b * 16 + h) * 128) * 4096 + n;
    for (int m = 0; m < 128; m++) {
        const float4* av = (const float4*)(a_s + m * 64);
        float s = 0.f;
#pragma unroll
        for (int i = 0; i < 16; i++) {
            float4 a4 = av[i];
            s += k[i].x * a4.x; s += k[i].y * a4.y;
            s += k[i].z * a4.z; s += k[i].w * a4.w;
        }
        out[(size_t)m * 4096] = s;
    }
}

// ---------------- ak: masked softmax over n (row length 4096), in place ----------------
// grid 8192 rows (b*h*m), block 256, 16 elems/thread.
__global__ __launch_bounds__(256) void k_ak_softmax() {
    const int bhm = blockIdx.x;
    const int b = bhm >> 11;          // / (16*128)
    float* row = g_ak + (size_t)bhm * 4096;
    const unsigned char* mrow = g_mask + b * 4096;
    const int t = threadIdx.x;

    float v[16];
    float mx = -3.402823e38f;
#pragma unroll
    for (int i = 0; i < 16; i++) {
        int n = t + i * 256;
        float xv = row[n];
        xv = mrow[n] ? xv : -3.402823e38f;
        v[i] = xv;
        mx = fmaxf(mx, xv);
    }
    __shared__ float red[256];
    red[t] = mx; __syncthreads();
    for (int s = 128; s > 0; s >>= 1) {
        if (t < s) red[t] = fmaxf(red[t], red[t + s]);
        __syncthreads();
    }
    mx = red[0]; __syncthreads();

    float sum = 0.f;
#pragma unroll
    for (int i = 0; i < 16; i++) { v[i] = __expf(v[i] - mx); sum += v[i]; }
    red[t] = sum; __syncthreads();
    for (int s = 128; s > 0; s >>= 1) {
        if (t < s) red[t] += red[t + s];
        __syncthreads();
    }
    const float inv = 1.f / red[0];
#pragma unroll
    for (int i = 0; i < 16; i++) row[t + i * 256] = v[i] * inv;
}

// ---------------- talking-heads mix: out[b,g,s] = sum_h W[g,h] * in[b,h,s] ----------------
// S = 128*4096 per (b,head). grid (2048, 4), block 256.
// NOTE: in/out are device globals referenced from DEVICE code (host-side symbol
// addresses of __device__ variables are invalid — GB300 ATS made that silent).
__device__ __forceinline__ void mix_body(const float* __restrict__ in,
                                         const float* __restrict__ W,
                                         float* __restrict__ out) {
    __shared__ float Ws[256];
    Ws[threadIdx.x] = W[threadIdx.x];
    __syncthreads();
    const size_t S = 524288;
    const int b = blockIdx.y;
    const size_t s = (size_t)blockIdx.x * 256 + threadIdx.x;
    float v[16];
#pragma unroll
    for (int h = 0; h < 16; h++) v[h] = in[(size_t)(b * 16 + h) * S + s];
#pragma unroll
    for (int g = 0; g < 16; g++) {
        float o = 0.f;
#pragma unroll
        for (int h = 0; h < 16; h++) o += Ws[g * 16 + h] * v[h];
        out[(size_t)(b * 16 + g) * S + s] = o;
    }
}

__global__ __launch_bounds__(256) void k_mix_qa(const float* __restrict__ W) {
    mix_body(g_qa, W, g_qam);
}
__global__ __launch_bounds__(256) void k_mix_ak(const float* __restrict__ W) {
    mix_body(g_ak, W, g_akm);
}

// ---------------- agent_out[b,g,m,d] = sum_n ak_mixed[b,g,m,n] * v[b,g,n,d] ----------------
// grid (16 g, 4 b), block 512. thread -> (d = t&63, mgroup = t>>6 of 16 m-rows).
__global__ __launch_bounds__(512) void k_agent_out() {
    __shared__ float akm_s[128 * 64];
    __shared__ float v_s[64 * 64];
    const int g = blockIdx.x, b = blockIdx.y;
    const int t = threadIdx.x;
    const int d = t & 63, mg = t >> 6;
    const float* akm_b = g_akm + (size_t)(b * 16 + g) * 128 * 4096;
    const float* v_b = g_qkv + (size_t)b * 4096 * 3072 + 2048 + g * 64;

    float acc[16];
#pragma unroll
    for (int j = 0; j < 16; j++) acc[j] = 0.f;

    for (int n0 = 0; n0 < 4096; n0 += 64) {
#pragma unroll
        for (int i = 0; i < 16; i++) {
            int idx = t + i * 512;
            int r = idx >> 6, c = idx & 63;
            akm_s[idx] = akm_b[(size_t)r * 4096 + n0 + c];
        }
#pragma unroll
        for (int i = 0; i < 8; i++) {
            int idx = t + i * 512;
            int r = idx >> 6, c = idx & 63;
            v_s[idx] = v_b[(size_t)(n0 + r) * 3072 + c];
        }
        __syncthreads();
#pragma unroll 4
        for (int nn = 0; nn < 64; nn++) {
            float vv = v_s[nn * 64 + d];
#pragma unroll
            for (int j = 0; j < 16; j++)
                acc[j] += akm_s[(mg * 16 + j) * 64 + nn] * vv;
        }
        __syncthreads();
    }
    float* out = g_ao + (size_t)(b * 16 + g) * 128 * 64;
#pragma unroll
    for (int j = 0; j < 16; j++) out[(mg * 16 + j) * 64 + d] = acc[j];
}

// ---------------- out_pre[b,n,g*64+d] = sum_m qa_mixed[b,g,m,n]*agent_out[b,g,m,d], masked ----
// grid (32 ntiles, 16 g, 4 b), block 256. thread -> (d = t&63, ngroup = t>>6 of 32 n-rows).
__global__ __launch_bounds__(256) void k_out_pre() {
    __shared__ float qam_s[64 * 128];
    __shared__ float ao_s[64 * 64];
    const int n0 = blockIdx.x * 128, g = blockIdx.y, b = blockIdx.z;
    const int t = threadIdx.x;
    const int d = t & 63, ng = t >> 6;
    const float* qam_b = g_qam + (size_t)(b * 16 + g) * 128 * 4096;
    const float* ao_b = g_ao + (size_t)(b * 16 + g) * 128 * 64;

    float acc[32];
#pragma unroll
    for (int j = 0; j < 32; j++) acc[j] = 0.f;

    for (int m0 = 0; m0 < 128; m0 += 64) {
#pragma unroll
        for (int i = 0; i < 32; i++) {
            int idx = t + i * 256;
            int r = idx >> 7, c = idx & 127;
            qam_s[idx] = qam_b[(size_t)(m0 + r) * 4096 + n0 + c];
        }
#pragma unroll
        for (int i = 0; i < 16; i++) {
            int idx = t + i * 256;
            ao_s[idx] = ao_b[m0 * 64 + idx];
        }
        __syncthreads();
#pragma unroll 2
        for (int mm = 0; mm < 64; mm++) {
            float av = ao_s[mm * 64 + d];
#pragma unroll
            for (int j = 0; j < 32; j++)
                acc[j] += qam_s[mm * 128 + ng * 32 + j] * av;
        }
        __syncthreads();
    }
#pragma unroll
    for (int j = 0; j < 32; j++) {
        int n = n0 + ng * 32 + j;
        float val = g_mask[b * 4096 + n] ? acc[j] : 0.f;
        g_outpre[((size_t)(b * 4096 + n)) * 1024 + g * 64 + d] = val;
    }
}

// ---------------- launch ----------------
extern "C" void kernel_launch(void* const* d_in, const int* in_sizes, int n_in,
                              void* d_out, int out_size) {
    const float* x = (const float*)d_in[0];
    const void* mask_raw = d_in[1];
    const float* W_qkv = (const float*)d_in[2];
    const float* agent = (const float*)d_in[3];
    const float* W_qa = (const float*)d_in[4];
    const float* W_ak = (const float*)d_in[5];
    const float* W_out = (const float*)d_in[6];
    float* out = (float*)d_out;

    // 0. canonicalize mask dtype -> g_mask (uint8)
    k_mask_canon<<<1, 256>>>(mask_raw);
    // 1. qkv projection
    k_qkv_gemm<<<dim3(3072 / 128, 16384 / 128), 256>>>(x, W_qkv);
    // 2. qa similarities + softmax (over m)
    k_qa<<<dim3(32, 16, 4), 128>>>(agent);
    // 3. ak similarities
    k_ak_sim<<<dim3(32, 16, 4), 128>>>(agent);
    // 4. masked softmax over n
    k_ak_softmax<<<8192, 256>>>();
    // 5. talking heads (device-global in/out referenced from device code)
    k_mix_qa<<<dim3(2048, 4), 256>>>(W_qa);
    k_mix_ak<<<dim3(2048, 4), 256>>>(W_ak);
    // 6. agent_out = ak_mixed @ v
    k_agent_out<<<dim3(16, 4), 512>>>();
    // 7. out_pre = qa_mixed^T @ agent_out (+ output mask)
    k_out_pre<<<dim3(32, 16, 4), 256>>>();
    // 8. final projection
    k_out_gemm<<<dim3(1024 / 128, 16384 / 128), 256>>>(W_out, out);
}

// round 4
// speedup vs baseline: 1.8995x; 1.8995x over previous
#include <cuda_runtime.h>
#include <math.h>

// Problem constants
// B=4, N=4096, DIM=1024, HEADS=16, DIM_HEAD=64, M=128, DIM_INNER=1024
// qkv layout: [b, n, 3*1024] with col = qkv_idx*1024 + h*64 + d
#define SCALE_A 0.125f   // 64^-0.5

// ---------------- scratch (device globals; no runtime allocation) ----------------
__device__ float g_qkv[50331648];    // [4,4096,3072]
__device__ float g_qa[33554432];     // qa_attn  [b,h,m=128,n=4096]  (n fastest)
__device__ float g_qam[33554432];    // qa mixed [b,g,m,n]
__device__ float g_ak[33554432];     // ak raw sims [b,h,m,n]
__device__ float g_akm[33554432];    // ak mixed (softmaxed) [b,g,m,n]
__device__ float2 g_akstat[8192];    // per (b,h,m): {rowmax, 1/sumexp}
__device__ float g_ao[524288];       // agent_out [b,g,m=128,d=64]
__device__ float g_outpre[16777216]; // [b,n,1024] pre-projection, masked
__device__ unsigned char g_mask[16384]; // canonical uint8 mask [b,n]

// ---------------- mask canonicalization ----------------
__global__ void k_mask_canon(const void* __restrict__ mraw) {
    __shared__ int notI32, notF32;
    if (threadIdx.x == 0) { notI32 = 0; notF32 = 0; }
    __syncthreads();
    const unsigned int* w = (const unsigned int*)mraw;
    int a = 0, b = 0;
    for (int i = threadIdx.x; i < 4096; i += 256) {
        unsigned int v = w[i];                      // first 16KB only
        if (v > 1u) a = 1;
        if (v != 0u && v != 0x3F800000u) b = 1;
    }
    if (a) atomicOr(&notI32, 1);
    if (b) atomicOr(&notF32, 1);
    __syncthreads();
    const int mode = notI32 ? (notF32 ? 2 : 1) : 0; // 0=int32, 1=float32, 2=uint8
    for (int i = threadIdx.x; i < 16384; i += 256) {
        unsigned char mv;
        if (mode == 0)      mv = (((const int*)mraw)[i] != 0);
        else if (mode == 1) mv = (((const float*)mraw)[i] != 0.0f);
        else                mv = (((const unsigned char*)mraw)[i] != 0);
        g_mask[i] = mv;
    }
}

// ---------------- tf32 tensor-core GEMM: C[M,N] = A[M,K] @ B[K,N] ----------------
// CTA tile 128x128, BK=32, 256 threads = 8 warps in 4(M)x2(N), warp tile 32x64.
// mma.sync.aligned.m16n8k8.row.col.f32.tf32.tf32.f32
__device__ __forceinline__ unsigned f2tf32(float x) {
    unsigned r;
    asm("cvt.rna.tf32.f32 %0, %1;" : "=r"(r) : "f"(x));
    return r;
}

__device__ __forceinline__ void mma_tf32(float* c, const unsigned* a,
                                         unsigned b0, unsigned b1) {
    asm volatile(
        "mma.sync.aligned.m16n8k8.row.col.f32.tf32.tf32.f32 "
        "{%0,%1,%2,%3}, {%4,%5,%6,%7}, {%8,%9}, {%0,%1,%2,%3};"
        : "+f"(c[0]), "+f"(c[1]), "+f"(c[2]), "+f"(c[3])
        : "r"(a[0]), "r"(a[1]), "r"(a[2]), "r"(a[3]), "r"(b0), "r"(b1));
}

__device__ __forceinline__ void gemm_tf32_body(const float* __restrict__ A,
                                               const float* __restrict__ B,
                                               float* __restrict__ C,
                                               int N, int K) {
    __shared__ unsigned As[128][36];   // [m][k], stride 36 words (conflict-free)
    __shared__ unsigned Bs[32][136];   // [k][n], stride 136 words (conflict-free)

    const int tid = threadIdx.x;
    const int warp = tid >> 5, lane = tid & 31;
    const int gid = lane >> 2, tig = lane & 3;
    const int wm = (warp & 3) * 32, wn = (warp >> 2) * 64;
    const int m0 = blockIdx.y * 128, n0 = blockIdx.x * 128;

    const float* Ab = A + (size_t)m0 * K;
    const float* Bb = B + n0;

    // per-thread staging coordinates
    const int ar = tid >> 3;            // A row 0..31 (x4 passes -> 0..127? no: f=tid+i*256)
    (void)ar;

    float acc[2][8][4];
#pragma unroll
    for (int i = 0; i < 2; i++)
#pragma unroll
        for (int j = 0; j < 8; j++)
#pragma unroll
            for (int l = 0; l < 4; l++) acc[i][j][l] = 0.f;

    float4 pa[4], pb[4];
    // prefetch tile 0
#pragma unroll
    for (int i = 0; i < 4; i++) {
        int f = tid + i * 256;
        int r = f >> 3, c = (f & 7) * 4;
        pa[i] = *(const float4*)(Ab + (size_t)r * K + c);
    }
#pragma unroll
    for (int i = 0; i < 4; i++) {
        int f = tid + i * 256;
        int kr = f >> 5, c = (f & 31) * 4;
        pb[i] = *(const float4*)(Bb + (size_t)kr * N + c);
    }

    for (int k0 = 0; k0 < K; k0 += 32) {
        // stage (with tf32 rounding) into smem
#pragma unroll
        for (int i = 0; i < 4; i++) {
            int f = tid + i * 256;
            int r = f >> 3, c = (f & 7) * 4;
            uint4 q = make_uint4(f2tf32(pa[i].x), f2tf32(pa[i].y),
                                 f2tf32(pa[i].z), f2tf32(pa[i].w));
            *(uint4*)&As[r][c] = q;
        }
#pragma unroll
        for (int i = 0; i < 4; i++) {
            int f = tid + i * 256;
            int kr = f >> 5, c = (f & 31) * 4;
            uint4 q = make_uint4(f2tf32(pb[i].x), f2tf32(pb[i].y),
                                 f2tf32(pb[i].z), f2tf32(pb[i].w));
            *(uint4*)&Bs[kr][c] = q;
        }
        __syncthreads();

        if (k0 + 32 < K) {
#pragma unroll
            for (int i = 0; i < 4; i++) {
                int f = tid + i * 256;
                int r = f >> 3, c = (f & 7) * 4;
                pa[i] = *(const float4*)(Ab + (size_t)r * K + (k0 + 32) + c);
            }
#pragma unroll
            for (int i = 0; i < 4; i++) {
                int f = tid + i * 256;
                int kr = f >> 5, c = (f & 31) * 4;
                pb[i] = *(const float4*)(Bb + (size_t)(k0 + 32 + kr) * N + c);
            }
        }

#pragma unroll
        for (int ks = 0; ks < 4; ks++) {
            const int kk = ks * 8;
            unsigned a[2][4];
#pragma unroll
            for (int mt = 0; mt < 2; mt++) {
                int r = wm + mt * 16 + gid;
                a[mt][0] = As[r][kk + tig];
                a[mt][1] = As[r + 8][kk + tig];
                a[mt][2] = As[r][kk + tig + 4];
                a[mt][3] = As[r + 8][kk + tig + 4];
            }
#pragma unroll
            for (int nt = 0; nt < 8; nt++) {
                unsigned b0 = Bs[kk + tig][wn + nt * 8 + gid];
                unsigned b1 = Bs[kk + tig + 4][wn + nt * 8 + gid];
                mma_tf32(acc[0][nt], a[0], b0, b1);
                mma_tf32(acc[1][nt], a[1], b0, b1);
            }
        }
        __syncthreads();
    }

    float* Cb = C + (size_t)m0 * N + n0;
#pragma unroll
    for (int mt = 0; mt < 2; mt++) {
#pragma unroll
        for (int nt = 0; nt < 8; nt++) {
            int r = wm + mt * 16 + gid;
            int c = wn + nt * 8 + tig * 2;
            *(float2*)(Cb + (size_t)r * N + c) =
                make_float2(acc[mt][nt][0], acc[mt][nt][1]);
            *(float2*)(Cb + (size_t)(r + 8) * N + c) =
                make_float2(acc[mt][nt][2], acc[mt][nt][3]);
        }
    }
}

__global__ __launch_bounds__(256, 2) void k_qkv_gemm(const float* __restrict__ x,
                                                     const float* __restrict__ Wqkv) {
    gemm_tf32_body(x, Wqkv, g_qkv, 3072, 1024);
}

__global__ __launch_bounds__(256, 2) void k_out_gemm(const float* __restrict__ Wout,
                                                     float* __restrict__ out) {
    gemm_tf32_body(g_outpre, Wout, out, 1024, 1024);
}

// ---------------- qa: sim + softmax(over m), store [b,h,m,n] ----------------
__global__ __launch_bounds__(128) void k_qa(const float* __restrict__ agent) {
    __shared__ float a_s[128 * 64];
    const int b = blockIdx.z, h = blockIdx.y, n0 = blockIdx.x * 128;
    const int t = threadIdx.x;
    for (int i = t; i < 128 * 64; i += 128) a_s[i] = agent[h * 8192 + i] * SCALE_A;
    __syncthreads();

    const int n = n0 + t;
    const float4* qrow = (const float4*)(g_qkv + ((size_t)(b * 4096 + n)) * 3072 + h * 64);
    float4 q[16];
#pragma unroll
    for (int i = 0; i < 16; i++) q[i] = qrow[i];

    float mx = -3.402823e38f, sum = 0.f;
    for (int m = 0; m < 128; m++) {
        const float4* av = (const float4*)(a_s + m * 64);
        float s = 0.f;
#pragma unroll
        for (int i = 0; i < 16; i++) {
            float4 a4 = av[i];
            s += q[i].x * a4.x; s += q[i].y * a4.y;
            s += q[i].z * a4.z; s += q[i].w * a4.w;
        }
        float nm = fmaxf(mx, s);
        sum = sum * __expf(mx - nm) + __expf(s - nm);
        mx = nm;
    }
    const float inv = 1.f / sum;
    float* out = g_qa + ((size_t)(b * 16 + h) * 128) * 4096 + n;
    for (int m = 0; m < 128; m++) {
        const float4* av = (const float4*)(a_s + m * 64);
        float s = 0.f;
#pragma unroll
        for (int i = 0; i < 16; i++) {
            float4 a4 = av[i];
            s += q[i].x * a4.x; s += q[i].y * a4.y;
            s += q[i].z * a4.z; s += q[i].w * a4.w;
        }
        out[(size_t)m * 4096] = __expf(s - mx) * inv;
    }
}

// ---------------- ak: raw sims [b,h,m,n] ----------------
__global__ __launch_bounds__(128) void k_ak_sim(const float* __restrict__ agent) {
    __shared__ float a_s[128 * 64];
    const int b = blockIdx.z, h = blockIdx.y, n0 = blockIdx.x * 128;
    const int t = threadIdx.x;
    for (int i = t; i < 128 * 64; i += 128) a_s[i] = agent[h * 8192 + i] * SCALE_A;
    __syncthreads();

    const int n = n0 + t;
    const float4* krow = (const float4*)(g_qkv + ((size_t)(b * 4096 + n)) * 3072 + 1024 + h * 64);
    float4 k[16];
#pragma unroll
    for (int i = 0; i < 16; i++) k[i] = krow[i];

    float* out = g_ak + ((size_t)(b * 16 + h) * 128) * 4096 + n;
    for (int m = 0; m < 128; m++) {
        const float4* av = (const float4*)(a_s + m * 64);
        float s = 0.f;
#pragma unroll
        for (int i = 0; i < 16; i++) {
            float4 a4 = av[i];
            s += k[i].x * a4.x; s += k[i].y * a4.y;
            s += k[i].z * a4.z; s += k[i].w * a4.w;
        }
        out[(size_t)m * 4096] = s;
    }
}

// ---------------- ak row stats: max + 1/sumexp per (b,h,m), masked ----------------
__global__ __launch_bounds__(256) void k_ak_stats() {
    const int bhm = blockIdx.x;
    const int b = bhm >> 11;
    const float* row = g_ak + (size_t)bhm * 4096;
    const unsigned char* mrow = g_mask + b * 4096;
    const int t = threadIdx.x;

    float v[16];
    float mx = -3.402823e38f;
#pragma unroll
    for (int i = 0; i < 16; i++) {
        int n = t + i * 256;
        float xv = row[n];
        xv = mrow[n] ? xv : -3.402823e38f;
        v[i] = xv;
        mx = fmaxf(mx, xv);
    }
    __shared__ float red[256];
    red[t] = mx; __syncthreads();
    for (int s = 128; s > 0; s >>= 1) {
        if (t < s) red[t] = fmaxf(red[t], red[t + s]);
        __syncthreads();
    }
    mx = red[0]; __syncthreads();

    float sum = 0.f;
#pragma unroll
    for (int i = 0; i < 16; i++) sum += __expf(v[i] - mx);
    red[t] = sum; __syncthreads();
    for (int s = 128; s > 0; s >>= 1) {
        if (t < s) red[t] += red[t + s];
        __syncthreads();
    }
    if (t == 0) g_akstat[bhm] = make_float2(mx, 1.f / red[0]);
}

// ---------------- talking-heads mixes ----------------
// qa: input already normalized. ak: normalize on the fly using stats.
__global__ __launch_bounds__(256) void k_mix_qa(const float* __restrict__ W) {
    __shared__ float Ws[256];
    Ws[threadIdx.x] = W[threadIdx.x];
    __syncthreads();
    const size_t S = 524288;
    const int b = blockIdx.y;
    const size_t s = (size_t)blockIdx.x * 256 + threadIdx.x;
    float v[16];
#pragma unroll
    for (int h = 0; h < 16; h++) v[h] = g_qa[(size_t)(b * 16 + h) * S + s];
#pragma unroll
    for (int g = 0; g < 16; g++) {
        float o = 0.f;
#pragma unroll
        for (int h = 0; h < 16; h++) o += Ws[g * 16 + h] * v[h];
        g_qam[(size_t)(b * 16 + g) * S + s] = o;
    }
}

__global__ __launch_bounds__(256) void k_mix_ak(const float* __restrict__ W) {
    __shared__ float Ws[256];
    Ws[threadIdx.x] = W[threadIdx.x];
    __syncthreads();
    const size_t S = 524288;
    const int b = blockIdx.y;
    const size_t s = (size_t)blockIdx.x * 256 + threadIdx.x;
    const int m = (int)(s >> 12);
    const int n = (int)(s & 4095);
    const unsigned char msk = g_mask[b * 4096 + n];
    float v[16];
#pragma unroll
    for (int h = 0; h < 16; h++) {
        float raw = g_ak[(size_t)(b * 16 + h) * S + s];
        float2 st = g_akstat[(b * 16 + h) * 128 + m];
        v[h] = msk ? __expf(raw - st.x) * st.y : 0.f;
    }
#pragma unroll
    for (int g = 0; g < 16; g++) {
        float o = 0.f;
#pragma unroll
        for (int h = 0; h < 16; h++) o += Ws[g * 16 + h] * v[h];
        g_akm[(size_t)(b * 16 + g) * S + s] = o;
    }
}

// ---------------- agent_out[b,g,m,d] = sum_n ak_mixed[b,g,m,n] * v[b,g,n,d] ----------------
__global__ __launch_bounds__(512) void k_agent_out() {
    __shared__ float akm_s[128 * 64];
    __shared__ float v_s[64 * 64];
    const int g = blockIdx.x, b = blockIdx.y;
    const int t = threadIdx.x;
    const int d = t & 63, mg = t >> 6;
    const float* akm_b = g_akm + (size_t)(b * 16 + g) * 128 * 4096;
    const float* v_b = g_qkv + (size_t)b * 4096 * 3072 + 2048 + g * 64;

    float acc[16];
#pragma unroll
    for (int j = 0; j < 16; j++) acc[j] = 0.f;

    for (int n0 = 0; n0 < 4096; n0 += 64) {
#pragma unroll
        for (int i = 0; i < 16; i++) {
            int idx = t + i * 512;
            int r = idx >> 6, c = idx & 63;
            akm_s[idx] = akm_b[(size_t)r * 4096 + n0 + c];
        }
#pragma unroll
        for (int i = 0; i < 8; i++) {
            int idx = t + i * 512;
            int r = idx >> 6, c = idx & 63;
            v_s[idx] = v_b[(size_t)(n0 + r) * 3072 + c];
        }
        __syncthreads();
#pragma unroll 4
        for (int nn = 0; nn < 64; nn++) {
            float vv = v_s[nn * 64 + d];
#pragma unroll
            for (int j = 0; j < 16; j++)
                acc[j] += akm_s[(mg * 16 + j) * 64 + nn] * vv;
        }
        __syncthreads();
    }
    float* out = g_ao + (size_t)(b * 16 + g) * 128 * 64;
#pragma unroll
    for (int j = 0; j < 16; j++) out[(mg * 16 + j) * 64 + d] = acc[j];
}

// ---------------- out_pre[b,n,g*64+d] = sum_m qa_mixed[b,g,m,n]*agent_out[b,g,m,d] ----------
__global__ __launch_bounds__(256) void k_out_pre() {
    __shared__ float qam_s[64 * 128];
    __shared__ float ao_s[64 * 64];
    const int n0 = blockIdx.x * 128, g = blockIdx.y, b = blockIdx.z;
    const int t = threadIdx.x;
    const int d = t & 63, ng = t >> 6;
    const float* qam_b = g_qam + (size_t)(b * 16 + g) * 128 * 4096;
    const float* ao_b = g_ao + (size_t)(b * 16 + g) * 128 * 64;

    float acc[32];
#pragma unroll
    for (int j = 0; j < 32; j++) acc[j] = 0.f;

    for (int m0 = 0; m0 < 128; m0 += 64) {
#pragma unroll
        for (int i = 0; i < 32; i++) {
            int idx = t + i * 256;
            int r = idx >> 7, c = idx & 127;
            qam_s[idx] = qam_b[(size_t)(m0 + r) * 4096 + n0 + c];
        }
#pragma unroll
        for (int i = 0; i < 16; i++) {
            int idx = t + i * 256;
            ao_s[idx] = ao_b[m0 * 64 + idx];
        }
        __syncthreads();
#pragma unroll 2
        for (int mm = 0; mm < 64; mm++) {
            float av = ao_s[mm * 64 + d];
#pragma unroll
            for (int j = 0; j < 32; j++)
                acc[j] += qam_s[mm * 128 + ng * 32 + j] * av;
        }
        __syncthreads();
    }
#pragma unroll
    for (int j = 0; j < 32; j++) {
        int n = n0 + ng * 32 + j;
        float val = g_mask[b * 4096 + n] ? acc[j] : 0.f;
        g_outpre[((size_t)(b * 4096 + n)) * 1024 + g * 64 + d] = val;
    }
}

// ---------------- launch ----------------
extern "C" void kernel_launch(void* const* d_in, const int* in_sizes, int n_in,
                              void* d_out, int out_size) {
    const float* x = (const float*)d_in[0];
    const void* mask_raw = d_in[1];
    const float* W_qkv = (const float*)d_in[2];
    const float* agent = (const float*)d_in[3];
    const float* W_qa = (const float*)d_in[4];
    const float* W_ak = (const float*)d_in[5];
    const float* W_out = (const float*)d_in[6];
    float* out = (float*)d_out;

    // 0. canonicalize mask dtype -> g_mask (uint8)
    k_mask_canon<<<1, 256>>>(mask_raw);
    // 1. qkv projection (tf32 tensor cores)
    k_qkv_gemm<<<dim3(3072 / 128, 16384 / 128), 256>>>(x, W_qkv);
    // 2. qa similarities + softmax (over m)
    k_qa<<<dim3(32, 16, 4), 128>>>(agent);
    // 3. ak similarities (raw)
    k_ak_sim<<<dim3(32, 16, 4), 128>>>(agent);
    // 4. ak row stats (masked max + 1/sumexp)
    k_ak_stats<<<8192, 256>>>();
    // 5. talking heads (ak mix applies softmax on the fly)
    k_mix_qa<<<dim3(2048, 4), 256>>>(W_qa);
    k_mix_ak<<<dim3(2048, 4), 256>>>(W_ak);
    // 6. agent_out = ak_mixed @ v
    k_agent_out<<<dim3(16, 4), 512>>>();
    // 7. out_pre = qa_mixed^T @ agent_out (+ output mask)
    k_out_pre<<<dim3(32, 16, 4), 256>>>();
    // 8. final projection (tf32 tensor cores)
    k_out_gemm<<<dim3(1024 / 128, 16384 / 128), 256>>>(W_out, out);
}

// round 5
// speedup vs baseline: 2.1422x; 1.1278x over previous
#include <cuda_runtime.h>
#include <math.h>

// Problem constants
// B=4, N=4096, DIM=1024, HEADS=16, DIM_HEAD=64, M=128, DIM_INNER=1024
// qkv layout: [b, n, 3*1024] with col = qkv_idx*1024 + h*64 + d
#define SCALE_A 0.125f   // 64^-0.5

// ---------------- scratch (device globals; no runtime allocation) ----------------
__device__ float g_qkv[50331648];    // [4,4096,3072]
__device__ float g_qa[33554432];     // qa_attn  [b,h,n,m]  (m fastest)  NEW LAYOUT
__device__ float g_qam[33554432];    // qa mixed [b,g,n,m]
__device__ float g_ak[33554432];     // ak raw sims [b,h,m,n] (n fastest)
__device__ float g_akm[33554432];    // ak mixed (softmaxed) [b,g,m,n]
__device__ float2 g_akstat[8192];    // per (b,h,m): {rowmax, 1/sumexp}
__device__ float g_ao[524288];       // agent_out [b,g,m=128,d=64]
__device__ float g_outpre[16777216]; // [b,n,1024] pre-projection, masked
__device__ unsigned char g_mask[16384]; // canonical uint8 mask [b,n]

// ---------------- mask canonicalization ----------------
__global__ void k_mask_canon(const void* __restrict__ mraw) {
    __shared__ int notI32, notF32;
    if (threadIdx.x == 0) { notI32 = 0; notF32 = 0; }
    __syncthreads();
    const unsigned int* w = (const unsigned int*)mraw;
    int a = 0, b = 0;
    for (int i = threadIdx.x; i < 4096; i += 256) {
        unsigned int v = w[i];                      // first 16KB only
        if (v > 1u) a = 1;
        if (v != 0u && v != 0x3F800000u) b = 1;
    }
    if (a) atomicOr(&notI32, 1);
    if (b) atomicOr(&notF32, 1);
    __syncthreads();
    const int mode = notI32 ? (notF32 ? 2 : 1) : 0; // 0=int32, 1=float32, 2=uint8
    for (int i = threadIdx.x; i < 16384; i += 256) {
        unsigned char mv;
        if (mode == 0)      mv = (((const int*)mraw)[i] != 0);
        else if (mode == 1) mv = (((const float*)mraw)[i] != 0.0f);
        else                mv = (((const unsigned char*)mraw)[i] != 0);
        g_mask[i] = mv;
    }
}

// ---------------- tf32 tensor-core GEMM (double-buffered): C = A @ B ----------------
// CTA tile 128x128, BK=32, 256 threads = 8 warps in 4(M)x2(N), warp tile 32x64.
__device__ __forceinline__ unsigned f2tf32(float x) {
    unsigned r;
    asm("cvt.rna.tf32.f32 %0, %1;" : "=r"(r) : "f"(x));
    return r;
}

__device__ __forceinline__ void mma_tf32(float* c, const unsigned* a,
                                         unsigned b0, unsigned b1) {
    asm volatile(
        "mma.sync.aligned.m16n8k8.row.col.f32.tf32.tf32.f32 "
        "{%0,%1,%2,%3}, {%4,%5,%6,%7}, {%8,%9}, {%0,%1,%2,%3};"
        : "+f"(c[0]), "+f"(c[1]), "+f"(c[2]), "+f"(c[3])
        : "r"(a[0]), "r"(a[1]), "r"(a[2]), "r"(a[3]), "r"(b0), "r"(b1));
}

#define GA_WORDS 4608            // 128*36
#define GB_WORDS 4352            // 32*136
#define GSTAGE_WORDS 8960        // GA + GB
#define GEMM_SMEM_BYTES (2 * GSTAGE_WORDS * 4)   // 71680

__device__ __forceinline__ void g_loadA(float4* pa, const float* __restrict__ Ab,
                                        int K, int k0, int tid) {
#pragma unroll
    for (int i = 0; i < 4; i++) {
        int f = tid + i * 256;
        int r = f >> 3, c = (f & 7) * 4;
        pa[i] = *(const float4*)(Ab + (size_t)r * K + k0 + c);
    }
}
__device__ __forceinline__ void g_loadB(float4* pb, const float* __restrict__ Bb,
                                        int N, int k0, int tid) {
#pragma unroll
    for (int i = 0; i < 4; i++) {
        int f = tid + i * 256;
        int kr = f >> 5, c = (f & 31) * 4;
        pb[i] = *(const float4*)(Bb + (size_t)(k0 + kr) * N + c);
    }
}
__device__ __forceinline__ void g_stage(unsigned* As, unsigned* Bs,
                                        const float4* pa, const float4* pb, int tid) {
#pragma unroll
    for (int i = 0; i < 4; i++) {
        int f = tid + i * 256;
        int r = f >> 3, c = (f & 7) * 4;
        uint4 q = make_uint4(f2tf32(pa[i].x), f2tf32(pa[i].y),
                             f2tf32(pa[i].z), f2tf32(pa[i].w));
        *(uint4*)&As[r * 36 + c] = q;
    }
#pragma unroll
    for (int i = 0; i < 4; i++) {
        int f = tid + i * 256;
        int kr = f >> 5, c = (f & 31) * 4;
        uint4 q = make_uint4(f2tf32(pb[i].x), f2tf32(pb[i].y),
                             f2tf32(pb[i].z), f2tf32(pb[i].w));
        *(uint4*)&Bs[kr * 136 + c] = q;
    }
}
__device__ __forceinline__ void g_compute(const unsigned* As, const unsigned* Bs,
                                          float acc[2][8][4],
                                          int wm, int wn, int gid, int tig) {
#pragma unroll
    for (int ks = 0; ks < 4; ks++) {
        const int kk = ks * 8;
        unsigned a[2][4];
#pragma unroll
        for (int mt = 0; mt < 2; mt++) {
            int r = wm + mt * 16 + gid;
            a[mt][0] = As[r * 36 + kk + tig];
            a[mt][1] = As[(r + 8) * 36 + kk + tig];
            a[mt][2] = As[r * 36 + kk + tig + 4];
            a[mt][3] = As[(r + 8) * 36 + kk + tig + 4];
        }
#pragma unroll
        for (int nt = 0; nt < 8; nt++) {
            unsigned b0 = Bs[(kk + tig) * 136 + wn + nt * 8 + gid];
            unsigned b1 = Bs[(kk + tig + 4) * 136 + wn + nt * 8 + gid];
            mma_tf32(acc[0][nt], a[0], b0, b1);
            mma_tf32(acc[1][nt], a[1], b0, b1);
        }
    }
}

__device__ __forceinline__ void gemm_tf32_body(const float* __restrict__ A,
                                               const float* __restrict__ B,
                                               float* __restrict__ C,
                                               int N, int K) {
    extern __shared__ unsigned dsm[];
    unsigned* As0 = dsm;
    unsigned* Bs0 = dsm + GA_WORDS;
    unsigned* As1 = dsm + GSTAGE_WORDS;
    unsigned* Bs1 = dsm + GSTAGE_WORDS + GA_WORDS;

    const int tid = threadIdx.x;
    const int warp = tid >> 5, lane = tid & 31;
    const int gid = lane >> 2, tig = lane & 3;
    const int wm = (warp & 3) * 32, wn = (warp >> 2) * 64;
    const int m0 = blockIdx.y * 128, n0 = blockIdx.x * 128;

    const float* Ab = A + (size_t)m0 * K;
    const float* Bb = B + n0;

    float acc[2][8][4];
#pragma unroll
    for (int i = 0; i < 2; i++)
#pragma unroll
        for (int j = 0; j < 8; j++)
#pragma unroll
            for (int l = 0; l < 4; l++) acc[i][j][l] = 0.f;

    float4 pa[4], pb[4];
    g_loadA(pa, Ab, K, 0, tid);
    g_loadB(pb, Bb, N, 0, tid);
    g_stage(As0, Bs0, pa, pb, tid);
    if (K > 32) { g_loadA(pa, Ab, K, 32, tid); g_loadB(pb, Bb, N, 32, tid); }
    __syncthreads();

    for (int k0 = 0; k0 < K; k0 += 32) {
        const int cur = (k0 >> 5) & 1;
        unsigned* Ac = cur ? As1 : As0;
        unsigned* Bc = cur ? Bs1 : Bs0;
        if (k0 + 32 < K) {
            unsigned* An = cur ? As0 : As1;
            unsigned* Bn = cur ? Bs0 : Bs1;
            g_stage(An, Bn, pa, pb, tid);
            if (k0 + 64 < K) {
                g_loadA(pa, Ab, K, k0 + 64, tid);
                g_loadB(pb, Bb, N, k0 + 64, tid);
            }
        }
        g_compute(Ac, Bc, acc, wm, wn, gid, tig);
        __syncthreads();
    }

    float* Cb = C + (size_t)m0 * N + n0;
#pragma unroll
    for (int mt = 0; mt < 2; mt++) {
#pragma unroll
        for (int nt = 0; nt < 8; nt++) {
            int r = wm + mt * 16 + gid;
            int c = wn + nt * 8 + tig * 2;
            *(float2*)(Cb + (size_t)r * N + c) =
                make_float2(acc[mt][nt][0], acc[mt][nt][1]);
            *(float2*)(Cb + (size_t)(r + 8) * N + c) =
                make_float2(acc[mt][nt][2], acc[mt][nt][3]);
        }
    }
}

__global__ __launch_bounds__(256, 2) void k_qkv_gemm(const float* __restrict__ x,
                                                     const float* __restrict__ Wqkv) {
    gemm_tf32_body(x, Wqkv, g_qkv, 3072, 1024);
}

__global__ __launch_bounds__(256, 2) void k_out_gemm(const float* __restrict__ Wout,
                                                     float* __restrict__ out) {
    gemm_tf32_body(g_outpre, Wout, out, 1024, 1024);
}

// ---------------- qa: register-tiled sim GEMM + fused softmax over m ----------------
// Block: (b, h, n-tile of 128). C[128n x 128m] = Q[128n,64] @ A^T[64,128m].
// 256 threads, thread tile 8n x 8m (split halves: idx t*4 and 64+t*4).
// Softmax over m fused (full m extent in block); writes p in [b,h,n,m] layout.
__global__ __launch_bounds__(256) void k_qa(const float* __restrict__ agent) {
    extern __shared__ float fsm[];
    float* Qs = fsm;          // [64k][128n]
    float* Ams = fsm + 8192;  // [64k][128m]
    const int b = blockIdx.z, h = blockIdx.y, n0 = blockIdx.x * 128;
    const int t = threadIdx.x;

    // load agent (scaled), transposed to [k][m]
    {
        int m = t >> 1, kb = (t & 1) * 32;
        const float4* src = (const float4*)(agent + h * 8192 + m * 64 + kb);
#pragma unroll
        for (int i = 0; i < 8; i++) {
            float4 v = src[i];
            int k = kb + i * 4;
            Ams[(k + 0) * 128 + m] = v.x * SCALE_A;
            Ams[(k + 1) * 128 + m] = v.y * SCALE_A;
            Ams[(k + 2) * 128 + m] = v.z * SCALE_A;
            Ams[(k + 3) * 128 + m] = v.w * SCALE_A;
        }
    }
    // load Q tile, transposed to [k][n]
    {
        int n = t >> 1, kb = (t & 1) * 32;
        const float4* src = (const float4*)(g_qkv + ((size_t)(b * 4096 + n0 + n)) * 3072 + h * 64 + kb);
#pragma unroll
        for (int i = 0; i < 8; i++) {
            float4 v = src[i];
            int k = kb + i * 4;
            Qs[(k + 0) * 128 + n] = v.x;
            Qs[(k + 1) * 128 + n] = v.y;
            Qs[(k + 2) * 128 + n] = v.z;
            Qs[(k + 3) * 128 + n] = v.w;
        }
    }
    __syncthreads();

    const int tx = t & 15, ty = t >> 4;
    float acc[8][8];
#pragma unroll
    for (int i = 0; i < 8; i++)
#pragma unroll
        for (int j = 0; j < 8; j++) acc[i][j] = 0.f;

#pragma unroll 4
    for (int kk = 0; kk < 64; kk++) {
        float4 q0 = *(const float4*)&Qs[kk * 128 + ty * 4];
        float4 q1 = *(const float4*)&Qs[kk * 128 + 64 + ty * 4];
        float4 a0 = *(const float4*)&Ams[kk * 128 + tx * 4];
        float4 a1 = *(const float4*)&Ams[kk * 128 + 64 + tx * 4];
        const float qn[8] = {q0.x, q0.y, q0.z, q0.w, q1.x, q1.y, q1.z, q1.w};
        const float am[8] = {a0.x, a0.y, a0.z, a0.w, a1.x, a1.y, a1.z, a1.w};
#pragma unroll
        for (int i = 0; i < 8; i++)
#pragma unroll
            for (int j = 0; j < 8; j++) acc[i][j] += qn[i] * am[j];
    }

    // fused softmax over m (across j in-thread + tx across 16 lanes)
    const size_t base = ((size_t)(b * 16 + h)) * 524288;
#pragma unroll
    for (int i = 0; i < 8; i++) {
        float mx = acc[i][0];
#pragma unroll
        for (int j = 1; j < 8; j++) mx = fmaxf(mx, acc[i][j]);
#pragma unroll
        for (int off = 8; off > 0; off >>= 1)
            mx = fmaxf(mx, __shfl_xor_sync(0xffffffffu, mx, off));
        float e[8], sum = 0.f;
#pragma unroll
        for (int j = 0; j < 8; j++) { e[j] = __expf(acc[i][j] - mx); sum += e[j]; }
#pragma unroll
        for (int off = 8; off > 0; off >>= 1)
            sum += __shfl_xor_sync(0xffffffffu, sum, off);
        const float inv = 1.f / sum;
        const int n_i = n0 + ((i < 4) ? (ty * 4 + i) : (64 + ty * 4 + i - 4));
        float* row = g_qa + base + (size_t)n_i * 128;
        *(float4*)(row + tx * 4) = make_float4(e[0] * inv, e[1] * inv, e[2] * inv, e[3] * inv);
        *(float4*)(row + 64 + tx * 4) = make_float4(e[4] * inv, e[5] * inv, e[6] * inv, e[7] * inv);
    }
}

// ---------------- ak: register-tiled sim GEMM, raw sims [b,h,m,n] ----------------
__global__ __launch_bounds__(256) void k_ak_sim(const float* __restrict__ agent) {
    extern __shared__ float fsm[];
    float* Ks = fsm;          // [64k][128n]
    float* Ams = fsm + 8192;  // [64k][128m]
    const int b = blockIdx.z, h = blockIdx.y, n0 = blockIdx.x * 128;
    const int t = threadIdx.x;

    {
        int m = t >> 1, kb = (t & 1) * 32;
        const float4* src = (const float4*)(agent + h * 8192 + m * 64 + kb);
#pragma unroll
        for (int i = 0; i < 8; i++) {
            float4 v = src[i];
            int k = kb + i * 4;
            Ams[(k + 0) * 128 + m] = v.x * SCALE_A;
            Ams[(k + 1) * 128 + m] = v.y * SCALE_A;
            Ams[(k + 2) * 128 + m] = v.z * SCALE_A;
            Ams[(k + 3) * 128 + m] = v.w * SCALE_A;
        }
    }
    {
        int n = t >> 1, kb = (t & 1) * 32;
        const float4* src = (const float4*)(g_qkv + ((size_t)(b * 4096 + n0 + n)) * 3072 + 1024 + h * 64 + kb);
#pragma unroll
        for (int i = 0; i < 8; i++) {
            float4 v = src[i];
            int k = kb + i * 4;
            Ks[(k + 0) * 128 + n] = v.x;
            Ks[(k + 1) * 128 + n] = v.y;
            Ks[(k + 2) * 128 + n] = v.z;
            Ks[(k + 3) * 128 + n] = v.w;
        }
    }
    __syncthreads();

    const int tx = t & 15, ty = t >> 4;    // tx -> n, ty -> m
    float acc[8][8];                        // [m][n]
#pragma unroll
    for (int i = 0; i < 8; i++)
#pragma unroll
        for (int j = 0; j < 8; j++) acc[i][j] = 0.f;

#pragma unroll 4
    for (int kk = 0; kk < 64; kk++) {
        float4 a0 = *(const float4*)&Ams[kk * 128 + ty * 4];
        float4 a1 = *(const float4*)&Ams[kk * 128 + 64 + ty * 4];
        float4 k0 = *(const float4*)&Ks[kk * 128 + tx * 4];
        float4 k1 = *(const float4*)&Ks[kk * 128 + 64 + tx * 4];
        const float am[8] = {a0.x, a0.y, a0.z, a0.w, a1.x, a1.y, a1.z, a1.w};
        const float kn[8] = {k0.x, k0.y, k0.z, k0.w, k1.x, k1.y, k1.z, k1.w};
#pragma unroll
        for (int i = 0; i < 8; i++)
#pragma unroll
            for (int j = 0; j < 8; j++) acc[i][j] += am[i] * kn[j];
    }

    const size_t base = ((size_t)(b * 16 + h)) * 524288;
#pragma unroll
    for (int i = 0; i < 8; i++) {
        const int m_i = (i < 4) ? (ty * 4 + i) : (64 + ty * 4 + i - 4);
        float* row = g_ak + base + (size_t)m_i * 4096 + n0;
        *(float4*)(row + tx * 4) = make_float4(acc[i][0], acc[i][1], acc[i][2], acc[i][3]);
        *(float4*)(row + 64 + tx * 4) = make_float4(acc[i][4], acc[i][5], acc[i][6], acc[i][7]);
    }
}

// ---------------- ak row stats: max + 1/sumexp per (b,h,m), masked ----------------
__global__ __launch_bounds__(256) void k_ak_stats() {
    const int bhm = blockIdx.x;
    const int b = bhm >> 11;
    const float* row = g_ak + (size_t)bhm * 4096;
    const unsigned char* mrow = g_mask + b * 4096;
    const int t = threadIdx.x;

    float v[16];
    float mx = -3.402823e38f;
#pragma unroll
    for (int i = 0; i < 16; i++) {
        int n = t + i * 256;
        float xv = row[n];
        xv = mrow[n] ? xv : -3.402823e38f;
        v[i] = xv;
        mx = fmaxf(mx, xv);
    }
    __shared__ float red[256];
    red[t] = mx; __syncthreads();
    for (int s = 128; s > 0; s >>= 1) {
        if (t < s) red[t] = fmaxf(red[t], red[t + s]);
        __syncthreads();
    }
    mx = red[0]; __syncthreads();

    float sum = 0.f;
#pragma unroll
    for (int i = 0; i < 16; i++) sum += __expf(v[i] - mx);
    red[t] = sum; __syncthreads();
    for (int s = 128; s > 0; s >>= 1) {
        if (t < s) red[t] += red[t + s];
        __syncthreads();
    }
    if (t == 0) g_akstat[bhm] = make_float2(mx, 1.f / red[0]);
}

// ---------------- talking-heads mixes ----------------
__global__ __launch_bounds__(256) void k_mix_qa(const float* __restrict__ W) {
    __shared__ float Ws[256];
    Ws[threadIdx.x] = W[threadIdx.x];
    __syncthreads();
    const size_t S = 524288;
    const int b = blockIdx.y;
    const size_t s = (size_t)blockIdx.x * 256 + threadIdx.x;
    float v[16];
#pragma unroll
    for (int h = 0; h < 16; h++) v[h] = g_qa[(size_t)(b * 16 + h) * S + s];
#pragma unroll
    for (int g = 0; g < 16; g++) {
        float o = 0.f;
#pragma unroll
        for (int h = 0; h < 16; h++) o += Ws[g * 16 + h] * v[h];
        g_qam[(size_t)(b * 16 + g) * S + s] = o;
    }
}

__global__ __launch_bounds__(256) void k_mix_ak(const float* __restrict__ W) {
    __shared__ float Ws[256];
    Ws[threadIdx.x] = W[threadIdx.x];
    __syncthreads();
    const size_t S = 524288;
    const int b = blockIdx.y;
    const size_t s = (size_t)blockIdx.x * 256 + threadIdx.x;
    const int m = (int)(s >> 12);
    const int n = (int)(s & 4095);
    const unsigned char msk = g_mask[b * 4096 + n];
    float v[16];
#pragma unroll
    for (int h = 0; h < 16; h++) {
        float raw = g_ak[(size_t)(b * 16 + h) * S + s];
        float2 st = g_akstat[(b * 16 + h) * 128 + m];
        v[h] = msk ? __expf(raw - st.x) * st.y : 0.f;
    }
#pragma unroll
    for (int g = 0; g < 16; g++) {
        float o = 0.f;
#pragma unroll
        for (int h = 0; h < 16; h++) o += Ws[g * 16 + h] * v[h];
        g_akm[(size_t)(b * 16 + g) * S + s] = o;
    }
}

// ---------------- agent_out[b,g,m,d] = sum_n ak_mixed[b,g,m,n] * v[b,g,n,d] ----------------
__global__ __launch_bounds__(512) void k_agent_out() {
    __shared__ float akm_s[128 * 64];
    __shared__ float v_s[64 * 64];
    const int g = blockIdx.x, b = blockIdx.y;
    const int t = threadIdx.x;
    const int d = t & 63, mg = t >> 6;
    const float* akm_b = g_akm + (size_t)(b * 16 + g) * 128 * 4096;
    const float* v_b = g_qkv + (size_t)b * 4096 * 3072 + 2048 + g * 64;

    float acc[16];
#pragma unroll
    for (int j = 0; j < 16; j++) acc[j] = 0.f;

    for (int n0 = 0; n0 < 4096; n0 += 64) {
#pragma unroll
        for (int i = 0; i < 16; i++) {
            int idx = t + i * 512;
            int r = idx >> 6, c = idx & 63;
            akm_s[idx] = akm_b[(size_t)r * 4096 + n0 + c];
        }
#pragma unroll
        for (int i = 0; i < 8; i++) {
            int idx = t + i * 512;
            int r = idx >> 6, c = idx & 63;
            v_s[idx] = v_b[(size_t)(n0 + r) * 3072 + c];
        }
        __syncthreads();
#pragma unroll 4
        for (int nn = 0; nn < 64; nn++) {
            float vv = v_s[nn * 64 + d];
#pragma unroll
            for (int j = 0; j < 16; j++)
                acc[j] += akm_s[(mg * 16 + j) * 64 + nn] * vv;
        }
        __syncthreads();
    }
    float* out = g_ao + (size_t)(b * 16 + g) * 128 * 64;
#pragma unroll
    for (int j = 0; j < 16; j++) out[(mg * 16 + j) * 64 + d] = acc[j];
}

// ---------------- out_pre: [b,n,g*64+d] = sum_m qam[b,g,n,m]*ao[b,g,m,d], masked ----
// Block (n-tile 128, g, b), 256 threads. Thread: tx->d (4), ty->n (8, split halves).
__global__ __launch_bounds__(256) void k_out_pre() {
    extern __shared__ float fsm[];
    float* qs = fsm;          // [64m][128n] (transposed chunk)
    float* aos = fsm + 8192;  // [128m][64d]
    const int n0 = blockIdx.x * 128, g = blockIdx.y, b = blockIdx.z;
    const int t = threadIdx.x;
    const int tx = t & 15, ty = t >> 4;
    const float* qam_b = g_qam + (size_t)(b * 16 + g) * 524288;
    const float* ao_b = g_ao + (size_t)(b * 16 + g) * 8192;

    // load agent_out once: [128m][64d]
#pragma unroll
    for (int i = 0; i < 8; i++) {
        int f = t + i * 256;
        int m = f >> 4, df = (f & 15) * 4;
        *(float4*)&aos[m * 64 + df] = *(const float4*)(ao_b + m * 64 + df);
    }

    float acc[8][4];
#pragma unroll
    for (int i = 0; i < 8; i++)
#pragma unroll
        for (int w = 0; w < 4; w++) acc[i][w] = 0.f;

    for (int mc = 0; mc < 128; mc += 64) {
        __syncthreads();
        // load qam chunk [128n][64m] -> transpose into qs[64m][128n]
#pragma unroll
        for (int i = 0; i < 8; i++) {
            int f = t + i * 256;
            int n = f >> 4, mf = (f & 15) * 4;
            float4 v = *(const float4*)(qam_b + (size_t)(n0 + n) * 128 + mc + mf);
            qs[(mf + 0) * 128 + n] = v.x;
            qs[(mf + 1) * 128 + n] = v.y;
            qs[(mf + 2) * 128 + n] = v.z;
            qs[(mf + 3) * 128 + n] = v.w;
        }
        __syncthreads();
#pragma unroll 4
        for (int mm = 0; mm < 64; mm++) {
            float4 r0 = *(const float4*)&qs[mm * 128 + ty * 4];
            float4 r1 = *(const float4*)&qs[mm * 128 + 64 + ty * 4];
            float4 rb = *(const float4*)&aos[(mc + mm) * 64 + tx * 4];
            const float rn[8] = {r0.x, r0.y, r0.z, r0.w, r1.x, r1.y, r1.z, r1.w};
            const float* bw = &rb.x;
#pragma unroll
            for (int i = 0; i < 8; i++)
#pragma unroll
                for (int w = 0; w < 4; w++) acc[i][w] += rn[i] * bw[w];
        }
    }

#pragma unroll
    for (int i = 0; i < 8; i++) {
        const int n_i = n0 + ((i < 4) ? (ty * 4 + i) : (64 + ty * 4 + i - 4));
        const float msk = g_mask[b * 4096 + n_i] ? 1.f : 0.f;
        *(float4*)(g_outpre + ((size_t)(b * 4096 + n_i)) * 1024 + g * 64 + tx * 4) =
            make_float4(acc[i][0] * msk, acc[i][1] * msk, acc[i][2] * msk, acc[i][3] * msk);
    }
}

// ---------------- launch ----------------
extern "C" void kernel_launch(void* const* d_in, const int* in_sizes, int n_in,
                              void* d_out, int out_size) {
    const float* x = (const float*)d_in[0];
    const void* mask_raw = d_in[1];
    const float* W_qkv = (const float*)d_in[2];
    const float* agent = (const float*)d_in[3];
    const float* W_qa = (const float*)d_in[4];
    const float* W_ak = (const float*)d_in[5];
    const float* W_out = (const float*)d_in[6];
    float* out = (float*)d_out;

    // opt into >48KB dynamic smem (immediate host calls; not stream ops)
    cudaFuncSetAttribute(k_qkv_gemm, cudaFuncAttributeMaxDynamicSharedMemorySize, GEMM_SMEM_BYTES);
    cudaFuncSetAttribute(k_out_gemm, cudaFuncAttributeMaxDynamicSharedMemorySize, GEMM_SMEM_BYTES);
    cudaFuncSetAttribute(k_qa, cudaFuncAttributeMaxDynamicSharedMemorySize, 65536);
    cudaFuncSetAttribute(k_ak_sim, cudaFuncAttributeMaxDynamicSharedMemorySize, 65536);
    cudaFuncSetAttribute(k_out_pre, cudaFuncAttributeMaxDynamicSharedMemorySize, 65536);

    // 0. canonicalize mask dtype -> g_mask (uint8)
    k_mask_canon<<<1, 256>>>(mask_raw);
    // 1. qkv projection (tf32 tensor cores, double-buffered)
    k_qkv_gemm<<<dim3(3072 / 128, 16384 / 128), 256, GEMM_SMEM_BYTES>>>(x, W_qkv);
    // 2. qa similarities + fused softmax (over m) -> [b,h,n,m]
    k_qa<<<dim3(32, 16, 4), 256, 65536>>>(agent);
    // 3. ak similarities (raw) -> [b,h,m,n]
    k_ak_sim<<<dim3(32, 16, 4), 256, 65536>>>(agent);
    // 4. ak row stats (masked max + 1/sumexp)
    k_ak_stats<<<8192, 256>>>();
    // 5. talking heads (ak mix applies softmax on the fly)
    k_mix_qa<<<dim3(2048, 4), 256>>>(W_qa);
    k_mix_ak<<<dim3(2048, 4), 256>>>(W_ak);
    // 6. agent_out = ak_mixed @ v
    k_agent_out<<<dim3(16, 4), 512>>>();
    // 7. out_pre = qam @ agent_out (+ output mask)
    k_out_pre<<<dim3(32, 16, 4), 256, 65536>>>();
    // 8. final projection (tf32 tensor cores)
    k_out_gemm<<<dim3(1024 / 128, 16384 / 128), 256, GEMM_SMEM_BYTES>>>(W_out, out);
}

// round 7
// speedup vs baseline: 2.1582x; 1.0075x over previous
#include <cuda_runtime.h>
#include <math.h>
#include <stdint.h>

// Problem constants
// B=4, N=4096, DIM=1024, HEADS=16, DIM_HEAD=64, M=128, DIM_INNER=1024
#define SCALE_A 0.125f   // 64^-0.5

// ---------------- scratch (device globals; no runtime allocation) ----------------
__device__ float g_qkv[50331648];    // [4,4096,3072]
__device__ float g_qa[33554432];     // qa_attn  [b,h,n,m]  (m fastest)
__device__ float g_qam[33554432];    // qa mixed [b,g,n,m]
__device__ float g_ak[33554432];     // ak raw sims [b,h,m,n] (n fastest)
__device__ float g_akm[33554432];    // ak mixed (softmaxed) [b,g,m,n]
__device__ float2 g_akstat[8192];    // per (b,h,m): {rowmax, 1/sumexp}
__device__ float g_ao[524288];       // agent_out [b,g,m=128,d=64]
__device__ float g_aop[2097152];     // agent_out partials [4 splits][b,g,m,d]
__device__ float g_outpre[16777216]; // [b,n,1024] pre-projection, masked
__device__ unsigned char g_mask[16384]; // canonical uint8 mask [b,n]

// ---------------- mask canonicalization ----------------
__global__ void k_mask_canon(const void* __restrict__ mraw) {
    __shared__ int notI32, notF32;
    if (threadIdx.x == 0) { notI32 = 0; notF32 = 0; }
    __syncthreads();
    const unsigned int* w = (const unsigned int*)mraw;
    int a = 0, b = 0;
    for (int i = threadIdx.x; i < 4096; i += 256) {
        unsigned int v = w[i];
        if (v > 1u) a = 1;
        if (v != 0u && v != 0x3F800000u) b = 1;
    }
    if (a) atomicOr(&notI32, 1);
    if (b) atomicOr(&notF32, 1);
    __syncthreads();
    const int mode = notI32 ? (notF32 ? 2 : 1) : 0; // 0=int32, 1=float32, 2=uint8
    for (int i = threadIdx.x; i < 16384; i += 256) {
        unsigned char mv;
        if (mode == 0)      mv = (((const int*)mraw)[i] != 0);
        else if (mode == 1) mv = (((const float*)mraw)[i] != 0.0f);
        else                mv = (((const unsigned char*)mraw)[i] != 0);
        g_mask[i] = mv;
    }
}

// ---------------- tf32 mma.sync GEMM with fragment-packed smem ----------------
// CTA tile 128x128, BK=32, 256 threads = 8 warps in 4(M)x2(N), warp tile 32x64.
__device__ __forceinline__ unsigned f2tf32(float x) {
    unsigned r;
    asm("cvt.rna.tf32.f32 %0, %1;" : "=r"(r) : "f"(x));
    return r;
}

__device__ __forceinline__ void mma_tf32(float* c, const unsigned* a,
                                         unsigned b0, unsigned b1) {
    asm volatile(
        "mma.sync.aligned.m16n8k8.row.col.f32.tf32.tf32.f32 "
        "{%0,%1,%2,%3}, {%4,%5,%6,%7}, {%8,%9}, {%0,%1,%2,%3};"
        : "+f"(c[0]), "+f"(c[1]), "+f"(c[2]), "+f"(c[3])
        : "r"(a[0]), "r"(a[1]), "r"(a[2]), "r"(a[3]), "r"(b0), "r"(b1));
}

// Packed buffers: A 4096 words (8 blk x 4 ks x 32 lanes x 4), B 4096 words
// (16 nblk x 4 ks x 32 lanes x 2). Stage = 8192 words = 32KB; double = 64KB.
#define GSTAGE_WORDS 8192
#define GEMM_SMEM_BYTES (2 * GSTAGE_WORDS * 4)   // 65536

__device__ __forceinline__ void g_loadA(float4* pa, const float* __restrict__ Ab,
                                        int K, int k0, int tid) {
#pragma unroll
    for (int i = 0; i < 4; i++) {
        int f = tid + i * 256;
        int r = f >> 3, c = (f & 7) * 4;
        pa[i] = *(const float4*)(Ab + (size_t)r * K + k0 + c);
    }
}
__device__ __forceinline__ void g_loadB(float4* pb, const float* __restrict__ Bb,
                                        int N, int k0, int tid) {
#pragma unroll
    for (int i = 0; i < 4; i++) {
        int f = tid + i * 256;
        int kr = f >> 5, c = (f & 31) * 4;
        pb[i] = *(const float4*)(Bb + (size_t)(k0 + kr) * N + c);
    }
}

// Stage into fragment order (with tf32 rounding).
// A element A[r][k]: blk=r>>4, gidE=r&7, ks=k>>3, tig=k&3, hi=(k>>2)&1,
//   j = hi*2 + ((r>>3)&1); quad = (blk*4+ks)*32 + ((gidE*4+tig)^ks); word=quad*4+j
// B element B[k][n]: nblk=n>>3, gidE=n&7, ks=k>>3, tig=k&3, v=(k>>2)&1;
//   pair = (nblk*4+ks)*32 + ((gidE*4+tig)^(nblk&15)); word=pair*2+v
__device__ __forceinline__ void g_stage(unsigned* buf, const float4* pa,
                                        const float4* pb, int tid) {
    unsigned* Ap = buf;
    unsigned* Bp = buf + 4096;
#pragma unroll
    for (int i = 0; i < 4; i++) {
        int f = tid + i * 256;
        int r = f >> 3, c = (f & 7) * 4;
        int ks = c >> 3, hi = (c >> 2) & 1;
        int blk = r >> 4, gidE = r & 7;
        int j = hi * 2 + ((r >> 3) & 1);
        const float* v = &pa[i].x;
#pragma unroll
        for (int jj = 0; jj < 4; jj++) {
            int lane_e = gidE * 4 + jj;
            int W = ((blk * 4 + ks) * 32 + (lane_e ^ ks)) * 4 + j;
            Ap[W] = f2tf32(v[jj]);
        }
    }
#pragma unroll
    for (int i = 0; i < 4; i++) {
        int f = tid + i * 256;
        int kr = f >> 5, c = (f & 31) * 4;
        int ks = kr >> 3, tig = kr & 3, vv = (kr >> 2) & 1;
        const float* v = &pb[i].x;
#pragma unroll
        for (int jj = 0; jj < 4; jj++) {
            int n = c + jj;
            int nblk = n >> 3, gidE = n & 7;
            int lane_e = gidE * 4 + tig;
            int W = ((nblk * 4 + ks) * 32 + (lane_e ^ (nblk & 15))) * 2 + vv;
            Bp[W] = f2tf32(v[jj]);
        }
    }
}

__device__ __forceinline__ void g_compute(const unsigned* buf, float acc[2][8][4],
                                          int wr, int wnblk, int lane) {
    const unsigned* Ap = buf;
    const unsigned* Bp = buf + 4096;
#pragma unroll
    for (int ks = 0; ks < 4; ks++) {
        unsigned a[2][4];
#pragma unroll
        for (int mt = 0; mt < 2; mt++) {
            int blk = wr * 2 + mt;
            uint4 q = *(const uint4*)&Ap[((blk * 4 + ks) * 32 + (lane ^ ks)) * 4];
            a[mt][0] = q.x; a[mt][1] = q.y; a[mt][2] = q.z; a[mt][3] = q.w;
        }
#pragma unroll
        for (int nt = 0; nt < 8; nt++) {
            int nblk = wnblk + nt;
            uint2 bb = *(const uint2*)&Bp[((nblk * 4 + ks) * 32 + (lane ^ (nblk & 15))) * 2];
            mma_tf32(acc[0][nt], a[0], bb.x, bb.y);
            mma_tf32(acc[1][nt], a[1], bb.x, bb.y);
        }
    }
}

__device__ __forceinline__ void gemm_tf32_body(const float* __restrict__ A,
                                               const float* __restrict__ B,
                                               float* __restrict__ C,
                                               int N, int K) {
    extern __shared__ unsigned dsm[];
    unsigned* buf0 = dsm;
    unsigned* buf1 = dsm + GSTAGE_WORDS;

    const int tid = threadIdx.x;
    const int warp = tid >> 5, lane = tid & 31;
    const int gid = lane >> 2, tig = lane & 3;
    const int wr = warp & 3, wn = (warp >> 2) * 64;
    const int wnblk = (warp >> 2) * 8;
    const int m0 = blockIdx.y * 128, n0 = blockIdx.x * 128;

    const float* Ab = A + (size_t)m0 * K;
    const float* Bb = B + n0;

    float acc[2][8][4];
#pragma unroll
    for (int i = 0; i < 2; i++)
#pragma unroll
        for (int j = 0; j < 8; j++)
#pragma unroll
            for (int l = 0; l < 4; l++) acc[i][j][l] = 0.f;

    float4 pa[4], pb[4];
    g_loadA(pa, Ab, K, 0, tid);
    g_loadB(pb, Bb, N, 0, tid);
    g_stage(buf0, pa, pb, tid);
    if (K > 32) { g_loadA(pa, Ab, K, 32, tid); g_loadB(pb, Bb, N, 32, tid); }
    __syncthreads();

    for (int k0 = 0; k0 < K; k0 += 32) {
        const int cur = (k0 >> 5) & 1;
        unsigned* bc = cur ? buf1 : buf0;
        if (k0 + 32 < K) {
            unsigned* bn = cur ? buf0 : buf1;
            g_stage(bn, pa, pb, tid);
            if (k0 + 64 < K) {
                g_loadA(pa, Ab, K, k0 + 64, tid);
                g_loadB(pb, Bb, N, k0 + 64, tid);
            }
        }
        g_compute(bc, acc, wr, wnblk, lane);
        __syncthreads();
    }

    float* Cb = C + (size_t)m0 * N + n0;
    const int wm = wr * 32;
#pragma unroll
    for (int mt = 0; mt < 2; mt++) {
#pragma unroll
        for (int nt = 0; nt < 8; nt++) {
            int r = wm + mt * 16 + gid;
            int c = wn + nt * 8 + tig * 2;
            *(float2*)(Cb + (size_t)r * N + c) =
                make_float2(acc[mt][nt][0], acc[mt][nt][1]);
            *(float2*)(Cb + (size_t)(r + 8) * N + c) =
                make_float2(acc[mt][nt][2], acc[mt][nt][3]);
        }
    }
}

__global__ __launch_bounds__(256, 2) void k_qkv_gemm(const float* __restrict__ x,
                                                     const float* __restrict__ Wqkv) {
    gemm_tf32_body(x, Wqkv, g_qkv, 3072, 1024);
}

__global__ __launch_bounds__(256, 2) void k_out_gemm(const float* __restrict__ Wout,
                                                     float* __restrict__ out) {
    gemm_tf32_body(g_outpre, Wout, out, 1024, 1024);
}

// ---------------- qa: register-tiled sim GEMM + fused softmax over m ----------------
__global__ __launch_bounds__(256) void k_qa(const float* __restrict__ agent) {
    extern __shared__ float fsm[];
    float* Qs = fsm;          // [64k][128n]
    float* Ams = fsm + 8192;  // [64k][128m]
    const int b = blockIdx.z, h = blockIdx.y, n0 = blockIdx.x * 128;
    const int t = threadIdx.x;

    {
        int m = t >> 1, kb = (t & 1) * 32;
        const float4* src = (const float4*)(agent + h * 8192 + m * 64 + kb);
#pragma unroll
        for (int i = 0; i < 8; i++) {
            float4 v = src[i];
            int k = kb + i * 4;
            Ams[(k + 0) * 128 + m] = v.x * SCALE_A;
            Ams[(k + 1) * 128 + m] = v.y * SCALE_A;
            Ams[(k + 2) * 128 + m] = v.z * SCALE_A;
            Ams[(k + 3) * 128 + m] = v.w * SCALE_A;
        }
    }
    {
        int n = t >> 1, kb = (t & 1) * 32;
        const float4* src = (const float4*)(g_qkv + ((size_t)(b * 4096 + n0 + n)) * 3072 + h * 64 + kb);
#pragma unroll
        for (int i = 0; i < 8; i++) {
            float4 v = src[i];
            int k = kb + i * 4;
            Qs[(k + 0) * 128 + n] = v.x;
            Qs[(k + 1) * 128 + n] = v.y;
            Qs[(k + 2) * 128 + n] = v.z;
            Qs[(k + 3) * 128 + n] = v.w;
        }
    }
    __syncthreads();

    const int tx = t & 15, ty = t >> 4;
    float acc[8][8];
#pragma unroll
    for (int i = 0; i < 8; i++)
#pragma unroll
        for (int j = 0; j < 8; j++) acc[i][j] = 0.f;

#pragma unroll 4
    for (int kk = 0; kk < 64; kk++) {
        float4 q0 = *(const float4*)&Qs[kk * 128 + ty * 4];
        float4 q1 = *(const float4*)&Qs[kk * 128 + 64 + ty * 4];
        float4 a0 = *(const float4*)&Ams[kk * 128 + tx * 4];
        float4 a1 = *(const float4*)&Ams[kk * 128 + 64 + tx * 4];
        const float qn[8] = {q0.x, q0.y, q0.z, q0.w, q1.x, q1.y, q1.z, q1.w};
        const float am[8] = {a0.x, a0.y, a0.z, a0.w, a1.x, a1.y, a1.z, a1.w};
#pragma unroll
        for (int i = 0; i < 8; i++)
#pragma unroll
            for (int j = 0; j < 8; j++) acc[i][j] += qn[i] * am[j];
    }

    const size_t base = ((size_t)(b * 16 + h)) * 524288;
#pragma unroll
    for (int i = 0; i < 8; i++) {
        float mx = acc[i][0];
#pragma unroll
        for (int j = 1; j < 8; j++) mx = fmaxf(mx, acc[i][j]);
#pragma unroll
        for (int off = 8; off > 0; off >>= 1)
            mx = fmaxf(mx, __shfl_xor_sync(0xffffffffu, mx, off));
        float e[8], sum = 0.f;
#pragma unroll
        for (int j = 0; j < 8; j++) { e[j] = __expf(acc[i][j] - mx); sum += e[j]; }
#pragma unroll
        for (int off = 8; off > 0; off >>= 1)
            sum += __shfl_xor_sync(0xffffffffu, sum, off);
        const float inv = 1.f / sum;
        const int n_i = n0 + ((i < 4) ? (ty * 4 + i) : (64 + ty * 4 + i - 4));
        float* row = g_qa + base + (size_t)n_i * 128;
        *(float4*)(row + tx * 4) = make_float4(e[0] * inv, e[1] * inv, e[2] * inv, e[3] * inv);
        *(float4*)(row + 64 + tx * 4) = make_float4(e[4] * inv, e[5] * inv, e[6] * inv, e[7] * inv);
    }
}

// ---------------- ak: register-tiled sim GEMM, raw sims [b,h,m,n] ----------------
__global__ __launch_bounds__(256) void k_ak_sim(const float* __restrict__ agent) {
    extern __shared__ float fsm[];
    float* Ks = fsm;          // [64k][128n]
    float* Ams = fsm + 8192;  // [64k][128m]
    const int b = blockIdx.z, h = blockIdx.y, n0 = blockIdx.x * 128;
    const int t = threadIdx.x;

    {
        int m = t >> 1, kb = (t & 1) * 32;
        const float4* src = (const float4*)(agent + h * 8192 + m * 64 + kb);
#pragma unroll
        for (int i = 0; i < 8; i++) {
            float4 v = src[i];
            int k = kb + i * 4;
            Ams[(k + 0) * 128 + m] = v.x * SCALE_A;
            Ams[(k + 1) * 128 + m] = v.y * SCALE_A;
            Ams[(k + 2) * 128 + m] = v.z * SCALE_A;
            Ams[(k + 3) * 128 + m] = v.w * SCALE_A;
        }
    }
    {
        int n = t >> 1, kb = (t & 1) * 32;
        const float4* src = (const float4*)(g_qkv + ((size_t)(b * 4096 + n0 + n)) * 3072 + 1024 + h * 64 + kb);
#pragma unroll
        for (int i = 0; i < 8; i++) {
            float4 v = src[i];
            int k = kb + i * 4;
            Ks[(k + 0) * 128 + n] = v.x;
            Ks[(k + 1) * 128 + n] = v.y;
            Ks[(k + 2) * 128 + n] = v.z;
            Ks[(k + 3) * 128 + n] = v.w;
        }
    }
    __syncthreads();

    const int tx = t & 15, ty = t >> 4;    // tx -> n, ty -> m
    float acc[8][8];
#pragma unroll
    for (int i = 0; i < 8; i++)
#pragma unroll
        for (int j = 0; j < 8; j++) acc[i][j] = 0.f;

#pragma unroll 4
    for (int kk = 0; kk < 64; kk++) {
        float4 a0 = *(const float4*)&Ams[kk * 128 + ty * 4];
        float4 a1 = *(const float4*)&Ams[kk * 128 + 64 + ty * 4];
        float4 k0 = *(const float4*)&Ks[kk * 128 + tx * 4];
        float4 k1 = *(const float4*)&Ks[kk * 128 + 64 + tx * 4];
        const float am[8] = {a0.x, a0.y, a0.z, a0.w, a1.x, a1.y, a1.z, a1.w};
        const float kn[8] = {k0.x, k0.y, k0.z, k0.w, k1.x, k1.y, k1.z, k1.w};
#pragma unroll
        for (int i = 0; i < 8; i++)
#pragma unroll
            for (int j = 0; j < 8; j++) acc[i][j] += am[i] * kn[j];
    }

    const size_t base = ((size_t)(b * 16 + h)) * 524288;
#pragma unroll
    for (int i = 0; i < 8; i++) {
        const int m_i = (i < 4) ? (ty * 4 + i) : (64 + ty * 4 + i - 4);
        float* row = g_ak + base + (size_t)m_i * 4096 + n0;
        *(float4*)(row + tx * 4) = make_float4(acc[i][0], acc[i][1], acc[i][2], acc[i][3]);
        *(float4*)(row + 64 + tx * 4) = make_float4(acc[i][4], acc[i][5], acc[i][6], acc[i][7]);
    }
}

// ---------------- ak row stats: max + 1/sumexp per (b,h,m), masked ----------------
__global__ __launch_bounds__(256) void k_ak_stats() {
    const int bhm = blockIdx.x;
    const int b = bhm >> 11;
    const float* row = g_ak + (size_t)bhm * 4096;
    const unsigned char* mrow = g_mask + b * 4096;
    const int t = threadIdx.x;

    float v[16];
    float mx = -3.402823e38f;
#pragma unroll
    for (int i = 0; i < 16; i++) {
        int n = t + i * 256;
        float xv = row[n];
        xv = mrow[n] ? xv : -3.402823e38f;
        v[i] = xv;
        mx = fmaxf(mx, xv);
    }
    __shared__ float red[256];
    red[t] = mx; __syncthreads();
    for (int s = 128; s > 0; s >>= 1) {
        if (t < s) red[t] = fmaxf(red[t], red[t + s]);
        __syncthreads();
    }
    mx = red[0]; __syncthreads();

    float sum = 0.f;
#pragma unroll
    for (int i = 0; i < 16; i++) sum += __expf(v[i] - mx);
    red[t] = sum; __syncthreads();
    for (int s = 128; s > 0; s >>= 1) {
        if (t < s) red[t] += red[t + s];
        __syncthreads();
    }
    if (t == 0) g_akstat[bhm] = make_float2(mx, 1.f / red[0]);
}

// ---------------- talking-heads mixes ----------------
__global__ __launch_bounds__(256) void k_mix_qa(const float* __restrict__ W) {
    __shared__ float Ws[256];
    Ws[threadIdx.x] = W[threadIdx.x];
    __syncthreads();
    const size_t S = 524288;
    const int b = blockIdx.y;
    const size_t s = (size_t)blockIdx.x * 256 + threadIdx.x;
    float v[16];
#pragma unroll
    for (int h = 0; h < 16; h++) v[h] = g_qa[(size_t)(b * 16 + h) * S + s];
#pragma unroll
    for (int g = 0; g < 16; g++) {
        float o = 0.f;
#pragma unroll
        for (int h = 0; h < 16; h++) o += Ws[g * 16 + h] * v[h];
        g_qam[(size_t)(b * 16 + g) * S + s] = o;
    }
}

__global__ __launch_bounds__(256) void k_mix_ak(const float* __restrict__ W) {
    __shared__ float Ws[256];
    Ws[threadIdx.x] = W[threadIdx.x];
    __syncthreads();
    const size_t S = 524288;
    const int b = blockIdx.y;
    const size_t s = (size_t)blockIdx.x * 256 + threadIdx.x;
    const int m = (int)(s >> 12);
    const int n = (int)(s & 4095);
    const unsigned char msk = g_mask[b * 4096 + n];
    float v[16];
#pragma unroll
    for (int h = 0; h < 16; h++) {
        float raw = g_ak[(size_t)(b * 16 + h) * S + s];
        float2 st = g_akstat[(b * 16 + h) * 128 + m];
        v[h] = msk ? __expf(raw - st.x) * st.y : 0.f;
    }
#pragma unroll
    for (int g = 0; g < 16; g++) {
        float o = 0.f;
#pragma unroll
        for (int h = 0; h < 16; h++) o += Ws[g * 16 + h] * v[h];
        g_akm[(size_t)(b * 16 + g) * S + s] = o;
    }
}

// ---------------- agent_out partials: split n into 4 ranges ----------------
// grid (16 g, 4 b, 4 split), block 512.
__global__ __launch_bounds__(512) void k_agent_out() {
    __shared__ float akm_s[128 * 64];
    __shared__ float v_s[64 * 64];
    const int g = blockIdx.x, b = blockIdx.y, sp = blockIdx.z;
    const int t = threadIdx.x;
    const int d = t & 63, mg = t >> 6;
    const float* akm_b = g_akm + (size_t)(b * 16 + g) * 128 * 4096;
    const float* v_b = g_qkv + (size_t)b * 4096 * 3072 + 2048 + g * 64;

    float acc[16];
#pragma unroll
    for (int j = 0; j < 16; j++) acc[j] = 0.f;

    const int nlo = sp * 1024, nhi = nlo + 1024;
    for (int n0 = nlo; n0 < nhi; n0 += 64) {
#pragma unroll
        for (int i = 0; i < 16; i++) {
            int idx = t + i * 512;
            int r = idx >> 6, c = idx & 63;
            akm_s[idx] = akm_b[(size_t)r * 4096 + n0 + c];
        }
#pragma unroll
        for (int i = 0; i < 8; i++) {
            int idx = t + i * 512;
            int r = idx >> 6, c = idx & 63;
            v_s[idx] = v_b[(size_t)(n0 + r) * 3072 + c];
        }
        __syncthreads();
#pragma unroll 4
        for (int nn = 0; nn < 64; nn++) {
            float vv = v_s[nn * 64 + d];
#pragma unroll
            for (int j = 0; j < 16; j++)
                acc[j] += akm_s[(mg * 16 + j) * 64 + nn] * vv;
        }
        __syncthreads();
    }
    float* out = g_aop + (size_t)sp * 524288 + (size_t)(b * 16 + g) * 8192;
#pragma unroll
    for (int j = 0; j < 16; j++) out[(mg * 16 + j) * 64 + d] = acc[j];
}

__global__ __launch_bounds__(256) void k_ao_reduce() {
    const int i = blockIdx.x * 256 + threadIdx.x;
    g_ao[i] = g_aop[i] + g_aop[524288 + i] + g_aop[1048576 + i] + g_aop[1572864 + i];
}

// ---------------- out_pre: [b,n,g*64+d] = sum_m qam[b,g,n,m]*ao[b,g,m,d], masked ----
__global__ __launch_bounds__(256) void k_out_pre() {
    extern __shared__ float fsm[];
    float* qs = fsm;          // [64m][128n]
    float* aos = fsm + 8192;  // [128m][64d]
    const int n0 = blockIdx.x * 128, g = blockIdx.y, b = blockIdx.z;
    const int t = threadIdx.x;
    const int tx = t & 15, ty = t >> 4;
    const float* qam_b = g_qam + (size_t)(b * 16 + g) * 524288;
    const float* ao_b = g_ao + (size_t)(b * 16 + g) * 8192;

#pragma unroll
    for (int i = 0; i < 8; i++) {
        int f = t + i * 256;
        int m = f >> 4, df = (f & 15) * 4;
        *(float4*)&aos[m * 64 + df] = *(const float4*)(ao_b + m * 64 + df);
    }

    float acc[8][4];
#pragma unroll
    for (int i = 0; i < 8; i++)
#pragma unroll
        for (int w = 0; w < 4; w++) acc[i][w] = 0.f;

    for (int mc = 0; mc < 128; mc += 64) {
        __syncthreads();
#pragma unroll
        for (int i = 0; i < 8; i++) {
            int f = t + i * 256;
            int n = f >> 4, mf = (f & 15) * 4;
            float4 v = *(const float4*)(qam_b + (size_t)(n0 + n) * 128 + mc + mf);
            qs[(mf + 0) * 128 + n] = v.x;
            qs[(mf + 1) * 128 + n] = v.y;
            qs[(mf + 2) * 128 + n] = v.z;
            qs[(mf + 3) * 128 + n] = v.w;
        }
        __syncthreads();
#pragma unroll 4
        for (int mm = 0; mm < 64; mm++) {
            float4 r0 = *(const float4*)&qs[mm * 128 + ty * 4];
            float4 r1 = *(const float4*)&qs[mm * 128 + 64 + ty * 4];
            float4 rb = *(const float4*)&aos[(mc + mm) * 64 + tx * 4];
            const float rn[8] = {r0.x, r0.y, r0.z, r0.w, r1.x, r1.y, r1.z, r1.w};
            const float* bw = &rb.x;
#pragma unroll
            for (int i = 0; i < 8; i++)
#pragma unroll
                for (int w = 0; w < 4; w++) acc[i][w] += rn[i] * bw[w];
        }
    }

#pragma unroll
    for (int i = 0; i < 8; i++) {
        const int n_i = n0 + ((i < 4) ? (ty * 4 + i) : (64 + ty * 4 + i - 4));
        const float msk = g_mask[b * 4096 + n_i] ? 1.f : 0.f;
        *(float4*)(g_outpre + ((size_t)(b * 4096 + n_i)) * 1024 + g * 64 + tx * 4) =
            make_float4(acc[i][0] * msk, acc[i][1] * msk, acc[i][2] * msk, acc[i][3] * msk);
    }
}

// ---------------- launch ----------------
extern "C" void kernel_launch(void* const* d_in, const int* in_sizes, int n_in,
                              void* d_out, int out_size) {
    const float* x = (const float*)d_in[0];
    const void* mask_raw = d_in[1];
    const float* W_qkv = (const float*)d_in[2];
    const float* agent = (const float*)d_in[3];
    const float* W_qa = (const float*)d_in[4];
    const float* W_ak = (const float*)d_in[5];
    const float* W_out = (const float*)d_in[6];
    float* out = (float*)d_out;

    cudaFuncSetAttribute(k_qkv_gemm, cudaFuncAttributeMaxDynamicSharedMemorySize, GEMM_SMEM_BYTES);
    cudaFuncSetAttribute(k_out_gemm, cudaFuncAttributeMaxDynamicSharedMemorySize, GEMM_SMEM_BYTES);
    cudaFuncSetAttribute(k_qa, cudaFuncAttributeMaxDynamicSharedMemorySize, 65536);
    cudaFuncSetAttribute(k_ak_sim, cudaFuncAttributeMaxDynamicSharedMemorySize, 65536);
    cudaFuncSetAttribute(k_out_pre, cudaFuncAttributeMaxDynamicSharedMemorySize, 65536);

    // 0. canonicalize mask dtype -> g_mask (uint8)
    k_mask_canon<<<1, 256>>>(mask_raw);
    // 1. qkv projection (tf32 mma.sync, fragment-packed smem)
    k_qkv_gemm<<<dim3(3072 / 128, 16384 / 128), 256, GEMM_SMEM_BYTES>>>(x, W_qkv);
    // 2. qa similarities + fused softmax (over m) -> [b,h,n,m]
    k_qa<<<dim3(32, 16, 4), 256, 65536>>>(agent);
    // 3. ak similarities (raw) -> [b,h,m,n]
    k_ak_sim<<<dim3(32, 16, 4), 256, 65536>>>(agent);
    // 4. ak row stats (masked max + 1/sumexp)
    k_ak_stats<<<8192, 256>>>();
    // 5. talking heads (ak mix applies softmax on the fly)
    k_mix_qa<<<dim3(2048, 4), 256>>>(W_qa);
    k_mix_ak<<<dim3(2048, 4), 256>>>(W_ak);
    // 6. agent_out = ak_mixed @ v (4-way n-split + reduce)
    k_agent_out<<<dim3(16, 4, 4), 512>>>();
    k_ao_reduce<<<2048, 256>>>();
    // 7. out_pre = qam @ agent_out (+ output mask)
    k_out_pre<<<dim3(32, 16, 4), 256, 65536>>>();
    // 8. final projection (tf32 mma.sync, fragment-packed smem)
    k_out_gemm<<<dim3(1024 / 128, 16384 / 128), 256, GEMM_SMEM_BYTES>>>(W_out, out);
}

// round 9
// speedup vs baseline: 2.6206x; 1.2142x over previous
#include <cuda_runtime.h>
#include <math.h>
#include <stdint.h>

// Problem constants
// B=4, N=4096, DIM=1024, HEADS=16, DIM_HEAD=64, M=128, DIM_INNER=1024
#define SCALE_A 0.125f   // 64^-0.5

// ---------------- scratch (device globals; no runtime allocation) ----------------
// RULE (learned R2, re-learned R8): device globals may ONLY be referenced from
// device code. Host-side symbol addresses are invalid (GB300 ATS makes it silent).
__device__ float g_qkv[50331648];    // [4,4096,3072]
__device__ float g_qa[33554432];     // qa_attn  [b,h,n,m]  (m fastest)
__device__ float g_qam[33554432];    // qa mixed [b,g,n,m]
__device__ float g_ak[33554432];     // ak raw sims [b,h,m,n] (n fastest)
__device__ float g_akm[33554432];    // ak mixed (softmaxed) [b,g,m,n]
__device__ float2 g_akstat[8192];    // per (b,h,m): {rowmax, 1/sumexp}
__device__ float g_ao[524288];       // agent_out [b,g,m=128,d=64]
__device__ float g_aop[2097152];     // agent_out partials [4 splits][b,g,m,d]
__device__ float g_outpre[16777216]; // [b,n,1024] pre-projection, masked
__device__ unsigned char g_mask[16384]; // canonical uint8 mask [b,n]
__device__ float g_pA[16777216];     // packed A (16384x1024), reused by both GEMMs
__device__ float g_pBq[3145728];     // packed W_qkv (1024x3072)
__device__ float g_pBo[1048576];     // packed W_out (1024x1024)

// ---------------- helpers ----------------
__device__ __forceinline__ unsigned f2tf32(float x) {
    unsigned r;
    asm("cvt.rna.tf32.f32 %0, %1;" : "=r"(r) : "f"(x));
    return r;
}
__device__ __forceinline__ uint32_t smem_u32(const void* p) {
    uint32_t a;
    asm("{ .reg .u64 t; cvta.to.shared.u64 t, %1; cvt.u32.u64 %0, t; }" : "=r"(a) : "l"(p));
    return a;
}
__device__ __forceinline__ void cp16(uint32_t saddr, const void* g) {
    asm volatile("cp.async.cg.shared.global [%0], [%1], 16;" :: "r"(saddr), "l"(g));
}
__device__ __forceinline__ void mma_tf32(float* c, const unsigned* a,
                                         unsigned b0, unsigned b1) {
    asm volatile(
        "mma.sync.aligned.m16n8k8.row.col.f32.tf32.tf32.f32 "
        "{%0,%1,%2,%3}, {%4,%5,%6,%7}, {%8,%9}, {%0,%1,%2,%3};"
        : "+f"(c[0]), "+f"(c[1]), "+f"(c[2]), "+f"(c[3])
        : "r"(a[0]), "r"(a[1]), "r"(a[2]), "r"(a[3]), "r"(b0), "r"(b1));
}

// ---------------- mask canonicalization ----------------
__global__ void k_mask_canon(const void* __restrict__ mraw) {
    __shared__ int notI32, notF32;
    if (threadIdx.x == 0) { notI32 = 0; notF32 = 0; }
    __syncthreads();
    const unsigned int* w = (const unsigned int*)mraw;
    int a = 0, b = 0;
    for (int i = threadIdx.x; i < 4096; i += 256) {
        unsigned int v = w[i];
        if (v > 1u) a = 1;
        if (v != 0u && v != 0x3F800000u) b = 1;
    }
    if (a) atomicOr(&notI32, 1);
    if (b) atomicOr(&notF32, 1);
    __syncthreads();
    const int mode = notI32 ? (notF32 ? 2 : 1) : 0;
    for (int i = threadIdx.x; i < 16384; i += 256) {
        unsigned char mv;
        if (mode == 0)      mv = (((const int*)mraw)[i] != 0);
        else if (mode == 1) mv = (((const float*)mraw)[i] != 0.0f);
        else                mv = (((const unsigned char*)mraw)[i] != 0);
        g_mask[i] = mv;
    }
}

// ---------------- operand pack bodies (tf32 round + fragment layout) ----------------
// A layout: for row r, col k (K cols):
//   rowtile=r>>8, blk=(r>>4)&15, gidE=r&7, hb=(r>>3)&1
//   c=k>>5, ks=(k>>3)&3, tig=k&3, hi=(k>>2)&1
//   lane=(gidE*4+tig)^ks, j=hi*2+hb
//   idx = (rowtile*(K/32)+c)*8192 + ((blk*4+ks)*32+lane)*4 + j
__device__ __forceinline__ void packA_body(const float* __restrict__ src,
                                           float* __restrict__ dst, int K) {
    const size_t t = (size_t)blockIdx.x * 256 + threadIdx.x;
    const int kq = K >> 2;
    const int r = (int)(t / kq);
    const int k4 = (int)(t % kq) * 4;
    float4 v = *(const float4*)(src + (size_t)r * K + k4);
    const int nc = K >> 5;
    const int rowtile = r >> 8, blk = (r >> 4) & 15, gidE = r & 7, hb = (r >> 3) & 1;
    float* base = dst + (size_t)rowtile * nc * 8192;
    const float vv[4] = {v.x, v.y, v.z, v.w};
#pragma unroll
    for (int e = 0; e < 4; e++) {
        int k = k4 + e;
        int c = k >> 5, ks = (k >> 3) & 3, tig = k & 3, hi = (k >> 2) & 1;
        int lane = (gidE * 4 + tig) ^ ks;
        int j = hi * 2 + hb;
        base[(size_t)c * 8192 + ((blk * 4 + ks) * 32 + lane) * 4 + j] =
            __uint_as_float(f2tf32(vv[e]));
    }
}

// B layout: W[k][n] row-major (K x N):
//   coltile=n>>7, nblk=(n>>3)&15, gidE=n&7
//   c=k>>5, ks=(k>>3)&3, tig=k&3, v=(k>>2)&1
//   lane=(gidE*4+tig)^nblk
//   idx = (coltile*(K/32)+c)*4096 + ((nblk*4+ks)*32+lane)*2 + v
__device__ __forceinline__ void packB_body(const float* __restrict__ src,
                                           float* __restrict__ dst, int N, int K) {
    const size_t t = (size_t)blockIdx.x * 256 + threadIdx.x;
    const int nq = N >> 2;
    const int k = (int)(t / nq);
    const int n4 = (int)(t % nq) * 4;
    float4 v = *(const float4*)(src + (size_t)k * N + n4);
    const int nc = K >> 5;
    const int c = k >> 5, ks = (k >> 3) & 3, tig = k & 3, vb = (k >> 2) & 1;
    const float vv[4] = {v.x, v.y, v.z, v.w};
#pragma unroll
    for (int e = 0; e < 4; e++) {
        int n = n4 + e;
        int coltile = n >> 7, nblk = (n >> 3) & 15, gidE = n & 7;
        int lane = (gidE * 4 + tig) ^ nblk;
        dst[((size_t)coltile * nc + c) * 4096 + ((nblk * 4 + ks) * 32 + lane) * 2 + vb] =
            __uint_as_float(f2tf32(vv[e]));
    }
}

// Wrappers: device globals bound in DEVICE code.
__global__ __launch_bounds__(256) void k_packA_x(const float* __restrict__ x) {
    packA_body(x, g_pA, 1024);
}
__global__ __launch_bounds__(256) void k_packA_outpre() {
    packA_body(g_outpre, g_pA, 1024);
}
__global__ __launch_bounds__(256) void k_packB_qkv(const float* __restrict__ w) {
    packB_body(w, g_pBq, 3072, 1024);
}
__global__ __launch_bounds__(256) void k_packB_out(const float* __restrict__ w) {
    packB_body(w, g_pBo, 1024, 1024);
}

// ---------------- packed tf32 GEMM: C[M,N] = A @ B ----------------
// CTA 256m x 128n, 8 warps (4m x 2n), warp tile 64x64, BK=32, cp.async double-buffer.
#define G2_STAGE_WORDS 12288          // A 8192 + B 4096
#define G2_SMEM_BYTES (2 * G2_STAGE_WORDS * 4)   // 98304

__device__ __forceinline__ void gemm_packed_body(const float* __restrict__ gA,
                                                 const float* __restrict__ gB,
                                                 float* __restrict__ C,
                                                 int N, int K) {
    extern __shared__ unsigned dsm[];
    unsigned* buf0 = dsm;
    unsigned* buf1 = dsm + G2_STAGE_WORDS;

    const int tid = threadIdx.x;
    const int warp = tid >> 5, lane = tid & 31;
    const int gid = lane >> 2, tig = lane & 3;
    const int wr = warp & 3, wq = warp >> 2;
    const int nc = K >> 5;

    const char* Asrc = (const char*)(gA + (size_t)blockIdx.y * nc * 8192);
    const char* Bsrc = (const char*)(gB + (size_t)blockIdx.x * nc * 4096);
    const uint32_t sA0 = smem_u32(buf0);
    const uint32_t sA1 = smem_u32(buf1);

    float acc[4][8][4];
#pragma unroll
    for (int i = 0; i < 4; i++)
#pragma unroll
        for (int j = 0; j < 8; j++)
#pragma unroll
            for (int l = 0; l < 4; l++) acc[i][j][l] = 0.f;

    auto issue = [&](uint32_t sbuf, int c) {
        const char* a = Asrc + (size_t)c * 32768;
        const char* b = Bsrc + (size_t)c * 16384;
#pragma unroll
        for (int i = 0; i < 8; i++) {
            int off = (tid + i * 256) * 16;
            cp16(sbuf + off, a + off);
        }
#pragma unroll
        for (int i = 0; i < 4; i++) {
            int off = (tid + i * 256) * 16;
            cp16(sbuf + 32768 + off, b + off);
        }
    };

    issue(sA0, 0);
    asm volatile("cp.async.commit_group;" ::: "memory");

    for (int c = 0; c < nc; c++) {
        const int cur = c & 1;
        if (c + 1 < nc) {
            issue(cur ? sA0 : sA1, c + 1);
            asm volatile("cp.async.commit_group;" ::: "memory");
            asm volatile("cp.async.wait_group 1;" ::: "memory");
        } else {
            asm volatile("cp.async.wait_group 0;" ::: "memory");
        }
        __syncthreads();
        const unsigned* Ap = cur ? buf1 : buf0;
        const unsigned* Bp = Ap + 8192;
#pragma unroll
        for (int ks = 0; ks < 4; ks++) {
            uint4 a[4];
#pragma unroll
            for (int mt = 0; mt < 4; mt++)
                a[mt] = *(const uint4*)&Ap[(((wr * 4 + mt) * 4 + ks) * 32 + (lane ^ ks)) * 4];
#pragma unroll
            for (int nt = 0; nt < 8; nt++) {
                int nblk = wq * 8 + nt;
                uint2 bb = *(const uint2*)&Bp[((nblk * 4 + ks) * 32 + (lane ^ nblk)) * 2];
#pragma unroll
                for (int mt = 0; mt < 4; mt++)
                    mma_tf32(acc[mt][nt], (const unsigned*)&a[mt], bb.x, bb.y);
            }
        }
        __syncthreads();
    }

    float* Cb = C + (size_t)(blockIdx.y * 256) * N + blockIdx.x * 128;
#pragma unroll
    for (int mt = 0; mt < 4; mt++) {
#pragma unroll
        for (int nt = 0; nt < 8; nt++) {
            int r = wr * 64 + mt * 16 + gid;
            int cc = wq * 64 + nt * 8 + tig * 2;
            *(float2*)(Cb + (size_t)r * N + cc) =
                make_float2(acc[mt][nt][0], acc[mt][nt][1]);
            *(float2*)(Cb + (size_t)(r + 8) * N + cc) =
                make_float2(acc[mt][nt][2], acc[mt][nt][3]);
        }
    }
}

// Wrappers: device globals bound in DEVICE code; only harness ptrs are args.
__global__ __launch_bounds__(256, 1) void k_gemm_qkv() {
    gemm_packed_body(g_pA, g_pBq, g_qkv, 3072, 1024);
}
__global__ __launch_bounds__(256, 1) void k_gemm_out(float* __restrict__ out) {
    gemm_packed_body(g_pA, g_pBo, out, 1024, 1024);
}

// ---------------- qa: register-tiled sim GEMM + fused softmax over m ----------------
__global__ __launch_bounds__(256) void k_qa(const float* __restrict__ agent) {
    extern __shared__ float fsm[];
    float* Qs = fsm;          // [64k][128n]
    float* Ams = fsm + 8192;  // [64k][128m]
    const int b = blockIdx.z, h = blockIdx.y, n0 = blockIdx.x * 128;
    const int t = threadIdx.x;

    {
        int m = t >> 1, kb = (t & 1) * 32;
        const float4* src = (const float4*)(agent + h * 8192 + m * 64 + kb);
#pragma unroll
        for (int i = 0; i < 8; i++) {
            float4 v = src[i];
            int k = kb + i * 4;
            Ams[(k + 0) * 128 + m] = v.x * SCALE_A;
            Ams[(k + 1) * 128 + m] = v.y * SCALE_A;
            Ams[(k + 2) * 128 + m] = v.z * SCALE_A;
            Ams[(k + 3) * 128 + m] = v.w * SCALE_A;
        }
    }
    {
        int n = t >> 1, kb = (t & 1) * 32;
        const float4* src = (const float4*)(g_qkv + ((size_t)(b * 4096 + n0 + n)) * 3072 + h * 64 + kb);
#pragma unroll
        for (int i = 0; i < 8; i++) {
            float4 v = src[i];
            int k = kb + i * 4;
            Qs[(k + 0) * 128 + n] = v.x;
            Qs[(k + 1) * 128 + n] = v.y;
            Qs[(k + 2) * 128 + n] = v.z;
            Qs[(k + 3) * 128 + n] = v.w;
        }
    }
    __syncthreads();

    const int tx = t & 15, ty = t >> 4;
    float acc[8][8];
#pragma unroll
    for (int i = 0; i < 8; i++)
#pragma unroll
        for (int j = 0; j < 8; j++) acc[i][j] = 0.f;

#pragma unroll 4
    for (int kk = 0; kk < 64; kk++) {
        float4 q0 = *(const float4*)&Qs[kk * 128 + ty * 4];
        float4 q1 = *(const float4*)&Qs[kk * 128 + 64 + ty * 4];
        float4 a0 = *(const float4*)&Ams[kk * 128 + tx * 4];
        float4 a1 = *(const float4*)&Ams[kk * 128 + 64 + tx * 4];
        const float qn[8] = {q0.x, q0.y, q0.z, q0.w, q1.x, q1.y, q1.z, q1.w};
        const float am[8] = {a0.x, a0.y, a0.z, a0.w, a1.x, a1.y, a1.z, a1.w};
#pragma unroll
        for (int i = 0; i < 8; i++)
#pragma unroll
            for (int j = 0; j < 8; j++) acc[i][j] += qn[i] * am[j];
    }

    const size_t base = ((size_t)(b * 16 + h)) * 524288;
#pragma unroll
    for (int i = 0; i < 8; i++) {
        float mx = acc[i][0];
#pragma unroll
        for (int j = 1; j < 8; j++) mx = fmaxf(mx, acc[i][j]);
#pragma unroll
        for (int off = 8; off > 0; off >>= 1)
            mx = fmaxf(mx, __shfl_xor_sync(0xffffffffu, mx, off));
        float e[8], sum = 0.f;
#pragma unroll
        for (int j = 0; j < 8; j++) { e[j] = __expf(acc[i][j] - mx); sum += e[j]; }
#pragma unroll
        for (int off = 8; off > 0; off >>= 1)
            sum += __shfl_xor_sync(0xffffffffu, sum, off);
        const float inv = 1.f / sum;
        const int n_i = n0 + ((i < 4) ? (ty * 4 + i) : (64 + ty * 4 + i - 4));
        float* row = g_qa + base + (size_t)n_i * 128;
        *(float4*)(row + tx * 4) = make_float4(e[0] * inv, e[1] * inv, e[2] * inv, e[3] * inv);
        *(float4*)(row + 64 + tx * 4) = make_float4(e[4] * inv, e[5] * inv, e[6] * inv, e[7] * inv);
    }
}

// ---------------- ak: register-tiled sim GEMM, raw sims [b,h,m,n] ----------------
__global__ __launch_bounds__(256) void k_ak_sim(const float* __restrict__ agent) {
    extern __shared__ float fsm[];
    float* Ks = fsm;          // [64k][128n]
    float* Ams = fsm + 8192;  // [64k][128m]
    const int b = blockIdx.z, h = blockIdx.y, n0 = blockIdx.x * 128;
    const int t = threadIdx.x;

    {
        int m = t >> 1, kb = (t & 1) * 32;
        const float4* src = (const float4*)(agent + h * 8192 + m * 64 + kb);
#pragma unroll
        for (int i = 0; i < 8; i++) {
            float4 v = src[i];
            int k = kb + i * 4;
            Ams[(k + 0) * 128 + m] = v.x * SCALE_A;
            Ams[(k + 1) * 128 + m] = v.y * SCALE_A;
            Ams[(k + 2) * 128 + m] = v.z * SCALE_A;
            Ams[(k + 3) * 128 + m] = v.w * SCALE_A;
        }
    }
    {
        int n = t >> 1, kb = (t & 1) * 32;
        const float4* src = (const float4*)(g_qkv + ((size_t)(b * 4096 + n0 + n)) * 3072 + 1024 + h * 64 + kb);
#pragma unroll
        for (int i = 0; i < 8; i++) {
            float4 v = src[i];
            int k = kb + i * 4;
            Ks[(k + 0) * 128 + n] = v.x;
            Ks[(k + 1) * 128 + n] = v.y;
            Ks[(k + 2) * 128 + n] = v.z;
            Ks[(k + 3) * 128 + n] = v.w;
        }
    }
    __syncthreads();

    const int tx = t & 15, ty = t >> 4;
    float acc[8][8];
#pragma unroll
    for (int i = 0; i < 8; i++)
#pragma unroll
        for (int j = 0; j < 8; j++) acc[i][j] = 0.f;

#pragma unroll 4
    for (int kk = 0; kk < 64; kk++) {
        float4 a0 = *(const float4*)&Ams[kk * 128 + ty * 4];
        float4 a1 = *(const float4*)&Ams[kk * 128 + 64 + ty * 4];
        float4 k0 = *(const float4*)&Ks[kk * 128 + tx * 4];
        float4 k1 = *(const float4*)&Ks[kk * 128 + 64 + tx * 4];
        const float am[8] = {a0.x, a0.y, a0.z, a0.w, a1.x, a1.y, a1.z, a1.w};
        const float kn[8] = {k0.x, k0.y, k0.z, k0.w, k1.x, k1.y, k1.z, k1.w};
#pragma unroll
        for (int i = 0; i < 8; i++)
#pragma unroll
            for (int j = 0; j < 8; j++) acc[i][j] += am[i] * kn[j];
    }

    const size_t base = ((size_t)(b * 16 + h)) * 524288;
#pragma unroll
    for (int i = 0; i < 8; i++) {
        const int m_i = (i < 4) ? (ty * 4 + i) : (64 + ty * 4 + i - 4);
        float* row = g_ak + base + (size_t)m_i * 4096 + n0;
        *(float4*)(row + tx * 4) = make_float4(acc[i][0], acc[i][1], acc[i][2], acc[i][3]);
        *(float4*)(row + 64 + tx * 4) = make_float4(acc[i][4], acc[i][5], acc[i][6], acc[i][7]);
    }
}

// ---------------- ak row stats: max + 1/sumexp per (b,h,m), masked ----------------
__global__ __launch_bounds__(256) void k_ak_stats() {
    const int bhm = blockIdx.x;
    const int b = bhm >> 11;
    const float* row = g_ak + (size_t)bhm * 4096;
    const unsigned char* mrow = g_mask + b * 4096;
    const int t = threadIdx.x;

    float v[16];
    float mx = -3.402823e38f;
#pragma unroll
    for (int i = 0; i < 16; i++) {
        int n = t + i * 256;
        float xv = row[n];
        xv = mrow[n] ? xv : -3.402823e38f;
        v[i] = xv;
        mx = fmaxf(mx, xv);
    }
    __shared__ float red[256];
    red[t] = mx; __syncthreads();
    for (int s = 128; s > 0; s >>= 1) {
        if (t < s) red[t] = fmaxf(red[t], red[t + s]);
        __syncthreads();
    }
    mx = red[0]; __syncthreads();

    float sum = 0.f;
#pragma unroll
    for (int i = 0; i < 16; i++) sum += __expf(v[i] - mx);
    red[t] = sum; __syncthreads();
    for (int s = 128; s > 0; s >>= 1) {
        if (t < s) red[t] += red[t + s];
        __syncthreads();
    }
    if (t == 0) g_akstat[bhm] = make_float2(mx, 1.f / red[0]);
}

// ---------------- talking-heads mixes ----------------
__global__ __launch_bounds__(256) void k_mix_qa(const float* __restrict__ W) {
    __shared__ float Ws[256];
    Ws[threadIdx.x] = W[threadIdx.x];
    __syncthreads();
    const size_t S = 524288;
    const int b = blockIdx.y;
    const size_t s = (size_t)blockIdx.x * 256 + threadIdx.x;
    float v[16];
#pragma unroll
    for (int h = 0; h < 16; h++) v[h] = g_qa[(size_t)(b * 16 + h) * S + s];
#pragma unroll
    for (int g = 0; g < 16; g++) {
        float o = 0.f;
#pragma unroll
        for (int h = 0; h < 16; h++) o += Ws[g * 16 + h] * v[h];
        g_qam[(size_t)(b * 16 + g) * S + s] = o;
    }
}

__global__ __launch_bounds__(256) void k_mix_ak(const float* __restrict__ W) {
    __shared__ float Ws[256];
    Ws[threadIdx.x] = W[threadIdx.x];
    __syncthreads();
    const size_t S = 524288;
    const int b = blockIdx.y;
    const size_t s = (size_t)blockIdx.x * 256 + threadIdx.x;
    const int m = (int)(s >> 12);
    const int n = (int)(s & 4095);
    const unsigned char msk = g_mask[b * 4096 + n];
    float v[16];
#pragma unroll
    for (int h = 0; h < 16; h++) {
        float raw = g_ak[(size_t)(b * 16 + h) * S + s];
        float2 st = g_akstat[(b * 16 + h) * 128 + m];
        v[h] = msk ? __expf(raw - st.x) * st.y : 0.f;
    }
#pragma unroll
    for (int g = 0; g < 16; g++) {
        float o = 0.f;
#pragma unroll
        for (int h = 0; h < 16; h++) o += Ws[g * 16 + h] * v[h];
        g_akm[(size_t)(b * 16 + g) * S + s] = o;
    }
}

// ---------------- agent_out partials: split n into 4 ranges ----------------
__global__ __launch_bounds__(512) void k_agent_out() {
    __shared__ float akm_s[128 * 64];
    __shared__ float v_s[64 * 64];
    const int g = blockIdx.x, b = blockIdx.y, sp = blockIdx.z;
    const int t = threadIdx.x;
    const int d = t & 63, mg = t >> 6;
    const float* akm_b = g_akm + (size_t)(b * 16 + g) * 128 * 4096;
    const float* v_b = g_qkv + (size_t)b * 4096 * 3072 + 2048 + g * 64;

    float acc[16];
#pragma unroll
    for (int j = 0; j < 16; j++) acc[j] = 0.f;

    const int nlo = sp * 1024, nhi = nlo + 1024;
    for (int n0 = nlo; n0 < nhi; n0 += 64) {
#pragma unroll
        for (int i = 0; i < 16; i++) {
            int idx = t + i * 512;
            int r = idx >> 6, c = idx & 63;
            akm_s[idx] = akm_b[(size_t)r * 4096 + n0 + c];
        }
#pragma unroll
        for (int i = 0; i < 8; i++) {
            int idx = t + i * 512;
            int r = idx >> 6, c = idx & 63;
            v_s[idx] = v_b[(size_t)(n0 + r) * 3072 + c];
        }
        __syncthreads();
#pragma unroll 4
        for (int nn = 0; nn < 64; nn++) {
            float vv = v_s[nn * 64 + d];
#pragma unroll
            for (int j = 0; j < 16; j++)
                acc[j] += akm_s[(mg * 16 + j) * 64 + nn] * vv;
        }
        __syncthreads();
    }
    float* out = g_aop + (size_t)sp * 524288 + (size_t)(b * 16 + g) * 8192;
#pragma unroll
    for (int j = 0; j < 16; j++) out[(mg * 16 + j) * 64 + d] = acc[j];
}

__global__ __launch_bounds__(256) void k_ao_reduce() {
    const int i = blockIdx.x * 256 + threadIdx.x;
    g_ao[i] = g_aop[i] + g_aop[524288 + i] + g_aop[1048576 + i] + g_aop[1572864 + i];
}

// ---------------- out_pre: [b,n,g*64+d] = sum_m qam[b,g,n,m]*ao[b,g,m,d], masked ----
__global__ __launch_bounds__(256) void k_out_pre() {
    extern __shared__ float fsm[];
    float* qs = fsm;          // [64m][128n]
    float* aos = fsm + 8192;  // [128m][64d]
    const int n0 = blockIdx.x * 128, g = blockIdx.y, b = blockIdx.z;
    const int t = threadIdx.x;
    const int tx = t & 15, ty = t >> 4;
    const float* qam_b = g_qam + (size_t)(b * 16 + g) * 524288;
    const float* ao_b = g_ao + (size_t)(b * 16 + g) * 8192;

#pragma unroll
    for (int i = 0; i < 8; i++) {
        int f = t + i * 256;
        int m = f >> 4, df = (f & 15) * 4;
        *(float4*)&aos[m * 64 + df] = *(const float4*)(ao_b + m * 64 + df);
    }

    float acc[8][4];
#pragma unroll
    for (int i = 0; i < 8; i++)
#pragma unroll
        for (int w = 0; w < 4; w++) acc[i][w] = 0.f;

    for (int mc = 0; mc < 128; mc += 64) {
        __syncthreads();
#pragma unroll
        for (int i = 0; i < 8; i++) {
            int f = t + i * 256;
            int n = f >> 4, mf = (f & 15) * 4;
            float4 v = *(const float4*)(qam_b + (size_t)(n0 + n) * 128 + mc + mf);
            qs[(mf + 0) * 128 + n] = v.x;
            qs[(mf + 1) * 128 + n] = v.y;
            qs[(mf + 2) * 128 + n] = v.z;
            qs[(mf + 3) * 128 + n] = v.w;
        }
        __syncthreads();
#pragma unroll 4
        for (int mm = 0; mm < 64; mm++) {
            float4 r0 = *(const float4*)&qs[mm * 128 + ty * 4];
            float4 r1 = *(const float4*)&qs[mm * 128 + 64 + ty * 4];
            float4 rb = *(const float4*)&aos[(mc + mm) * 64 + tx * 4];
            const float rn[8] = {r0.x, r0.y, r0.z, r0.w, r1.x, r1.y, r1.z, r1.w};
            const float* bw = &rb.x;
#pragma unroll
            for (int i = 0; i < 8; i++)
#pragma unroll
                for (int w = 0; w < 4; w++) acc[i][w] += rn[i] * bw[w];
        }
    }

#pragma unroll
    for (int i = 0; i < 8; i++) {
        const int n_i = n0 + ((i < 4) ? (ty * 4 + i) : (64 + ty * 4 + i - 4));
        const float msk = g_mask[b * 4096 + n_i] ? 1.f : 0.f;
        *(float4*)(g_outpre + ((size_t)(b * 4096 + n_i)) * 1024 + g * 64 + tx * 4) =
            make_float4(acc[i][0] * msk, acc[i][1] * msk, acc[i][2] * msk, acc[i][3] * msk);
    }
}

// ---------------- launch ----------------
extern "C" void kernel_launch(void* const* d_in, const int* in_sizes, int n_in,
                              void* d_out, int out_size) {
    const float* x = (const float*)d_in[0];
    const void* mask_raw = d_in[1];
    const float* W_qkv = (const float*)d_in[2];
    const float* agent = (const float*)d_in[3];
    const float* W_qa = (const float*)d_in[4];
    const float* W_ak = (const float*)d_in[5];
    const float* W_out = (const float*)d_in[6];
    float* out = (float*)d_out;

    cudaFuncSetAttribute(k_gemm_qkv, cudaFuncAttributeMaxDynamicSharedMemorySize, G2_SMEM_BYTES);
    cudaFuncSetAttribute(k_gemm_out, cudaFuncAttributeMaxDynamicSharedMemorySize, G2_SMEM_BYTES);
    cudaFuncSetAttribute(k_qa, cudaFuncAttributeMaxDynamicSharedMemorySize, 65536);
    cudaFuncSetAttribute(k_ak_sim, cudaFuncAttributeMaxDynamicSharedMemorySize, 65536);
    cudaFuncSetAttribute(k_out_pre, cudaFuncAttributeMaxDynamicSharedMemorySize, 65536);

    // 0. mask canonicalization + operand packing
    k_mask_canon<<<1, 256>>>(mask_raw);
    k_packB_qkv<<<3072, 256>>>(W_qkv);
    k_packB_out<<<1024, 256>>>(W_out);
    k_packA_x<<<16384, 256>>>(x);
    // 1. qkv projection
    k_gemm_qkv<<<dim3(3072 / 128, 16384 / 256), 256, G2_SMEM_BYTES>>>();
    // 2. qa similarities + fused softmax (over m) -> [b,h,n,m]
    k_qa<<<dim3(32, 16, 4), 256, 65536>>>(agent);
    // 3. ak similarities (raw) -> [b,h,m,n]
    k_ak_sim<<<dim3(32, 16, 4), 256, 65536>>>(agent);
    // 4. ak row stats (masked max + 1/sumexp)
    k_ak_stats<<<8192, 256>>>();
    // 5. talking heads (ak mix applies softmax on the fly)
    k_mix_qa<<<dim3(2048, 4), 256>>>(W_qa);
    k_mix_ak<<<dim3(2048, 4), 256>>>(W_ak);
    // 6. agent_out = ak_mixed @ v (4-way n-split + reduce)
    k_agent_out<<<dim3(16, 4, 4), 512>>>();
    k_ao_reduce<<<2048, 256>>>();
    // 7. out_pre = qam @ agent_out (+ output mask)
    k_out_pre<<<dim3(32, 16, 4), 256, 65536>>>();
    // 8. final projection (pack outpre, then packed GEMM)
    k_packA_outpre<<<16384, 256>>>();
    k_gemm_out<<<dim3(1024 / 128, 16384 / 256), 256, G2_SMEM_BYTES>>>(out);
}